// round 1
// baseline (speedup 1.0000x reference)
#include <cuda_runtime.h>

#define NPTS 32768
#define CH   128
#define TM   128          // rows per CTA
#define KC   32           // ci chunk
#define NT   256          // threads per CTA
#define SMEM_FLOATS (TM*CH + KC*CH + TM)
#define SMEM_BYTES  (SMEM_FLOATS * 4)

// ---- scratch (device globals; no allocation allowed) ----
__device__ __align__(16) float g_A[NPTS*CH];     // x @ Wa1
__device__ __align__(16) float g_V[NPTS*CH];     // x @ Wv1
__device__ __align__(16) float g_G[NPTS*CH];     // conv5(A) * V
__device__ __align__(16) float g_Y[NPTS*CH];     // conv pre-BN output (reused)
__device__ __align__(16) float g_R[NPTS*CH];     // residual2
__device__ __align__(16) float g_T[NPTS*CH];     // relu(BN1 + x)
__device__ __align__(16) float g_part[2*64*256]; // BN partial sums
__device__ __align__(16) float g_scale[CH];
__device__ __align__(16) float g_shift[CH];

// ============================================================================
// Generic gather-GEMM-accumulate:
//   out[i, co] (opt *gate[i,co]) = sum_{k<K} sum_ci feats[nbr[i,k], ci] * W[k,ci,co]
// nbr == nullptr -> identity gather (dense GEMM).
// CTA: 128 rows x 128 cols. 256 threads, each 8x8 register tile.
// ============================================================================
__global__ void __launch_bounds__(NT, 2)
sconv_kernel(const float* __restrict__ feats,
             const float* __restrict__ Wt,     // [K][CH][CH]
             const int*   __restrict__ nbr,    // [NPTS][K] or nullptr
             const int K,
             const float* __restrict__ gate,   // [NPTS][CH] or nullptr
             float* __restrict__ out)
{
    extern __shared__ float smem[];
    float* Fs   = smem;                         // [TM][CH]  gathered rows
    float* Ws   = smem + TM*CH;                 // [KC][CH]  weight chunk
    int*   sIdx = (int*)(smem + TM*CH + KC*CH); // [TM]

    const int tid  = threadIdx.x;
    const int row0 = blockIdx.x * TM;
    const int tcx  = tid & 15;   // col group: cols tcx*8 .. +8
    const int tcy  = tid >> 4;   // row group: rows tcy*8 .. +8

    float acc[8][8];
#pragma unroll
    for (int r = 0; r < 8; ++r)
#pragma unroll
        for (int c = 0; c < 8; ++c) acc[r][c] = 0.f;

    for (int k = 0; k < K; ++k) {
        __syncthreads();   // prior compute done before overwriting Fs / sIdx
        if (tid < TM)
            sIdx[tid] = nbr ? nbr[(row0 + tid) * K + k] : (row0 + tid);
        __syncthreads();

        // gather 128 feature rows (512B each, coalesced from L2)
#pragma unroll
        for (int j = 0; j < (TM*CH/4)/NT; ++j) {    // 16 iters of float4
            int lin = tid + j*NT;
            int r   = lin >> 5;          // 32 float4 per row
            int c4  = lin & 31;
            float4 v = reinterpret_cast<const float4*>(feats + (size_t)sIdx[r]*CH)[c4];
            reinterpret_cast<float4*>(Fs + r*CH)[c4] = v;
        }

        const float* Wk = Wt + (size_t)k * (CH*CH);
#pragma unroll 1
        for (int cc = 0; cc < CH/KC; ++cc) {
            __syncthreads();
            // load 32x128 weight chunk (contiguous)
#pragma unroll
            for (int j = 0; j < 4; ++j) {
                int lin = tid + j*NT;   // 0..1023 float4
                reinterpret_cast<float4*>(Ws)[lin] =
                    reinterpret_cast<const float4*>(Wk + cc*(KC*CH))[lin];
            }
            __syncthreads();

            const float*  fp   = Fs + (tcy*8)*CH + cc*KC;
            const float4* wrow = reinterpret_cast<const float4*>(Ws);
#pragma unroll 4
            for (int ci = 0; ci < KC; ++ci) {
                float f[8];
#pragma unroll
                for (int r = 0; r < 8; ++r) f[r] = fp[r*CH + ci];
                float4 w0 = wrow[ci*(CH/4) + tcx*2];
                float4 w1 = wrow[ci*(CH/4) + tcx*2 + 1];
                float w[8] = {w0.x, w0.y, w0.z, w0.w, w1.x, w1.y, w1.z, w1.w};
#pragma unroll
                for (int r = 0; r < 8; ++r)
#pragma unroll
                    for (int c = 0; c < 8; ++c)
                        acc[r][c] = fmaf(f[r], w[c], acc[r][c]);
            }
        }
    }

    // epilogue (optional elementwise gate fused in)
#pragma unroll
    for (int r = 0; r < 8; ++r) {
        size_t base = (size_t)(row0 + tcy*8 + r)*CH + tcx*8;
        float o[8];
#pragma unroll
        for (int c = 0; c < 8; ++c) o[c] = acc[r][c];
        if (gate) {
            float4 g0 = *reinterpret_cast<const float4*>(gate + base);
            float4 g1 = *reinterpret_cast<const float4*>(gate + base + 4);
            o[0]*=g0.x; o[1]*=g0.y; o[2]*=g0.z; o[3]*=g0.w;
            o[4]*=g1.x; o[5]*=g1.y; o[6]*=g1.z; o[7]*=g1.w;
        }
        *reinterpret_cast<float4*>(out + base)     = make_float4(o[0],o[1],o[2],o[3]);
        *reinterpret_cast<float4*>(out + base + 4) = make_float4(o[4],o[5],o[6],o[7]);
    }
}

// ============================================================================
// BatchNorm: deterministic two-stage reduction over N per channel.
// ============================================================================
__global__ void bn_partial_kernel(const float* __restrict__ y)
{
    int tid  = threadIdx.x;          // 256
    int c    = tid & (CH-1);
    int half = tid >> 7;
    int rbase = blockIdx.x * 512 + half;
    float s = 0.f, s2 = 0.f;
#pragma unroll 8
    for (int j = 0; j < 256; ++j) {
        float v = y[(size_t)(rbase + 2*j)*CH + c];
        s += v;
        s2 = fmaf(v, v, s2);
    }
    g_part[blockIdx.x*256 + tid]          = s;
    g_part[64*256 + blockIdx.x*256 + tid] = s2;
}

__global__ void bn_finalize_kernel(const float* __restrict__ gamma,
                                   const float* __restrict__ beta)
{
    int c = threadIdx.x;  // 128
    float s = 0.f, s2 = 0.f;
    for (int b = 0; b < 64; ++b) {
        s  += g_part[b*256 + c]          + g_part[b*256 + CH + c];
        s2 += g_part[64*256 + b*256 + c] + g_part[64*256 + b*256 + CH + c];
    }
    const float inv = 1.0f / (float)NPTS;
    float mu  = s * inv;
    float var = s2 * inv - mu*mu;
    float sc  = gamma[c] * rsqrtf(var + 1e-5f);
    g_scale[c] = sc;
    g_shift[c] = fmaf(-mu, sc, beta[c]);
}

// r2 = BN1(y) + x ; T = relu(r2)
__global__ void ew1_kernel(const float* __restrict__ y, const float* __restrict__ x)
{
    size_t i = (size_t)blockIdx.x * blockDim.x + threadIdx.x;  // float4 index
    float4 yv = reinterpret_cast<const float4*>(y)[i];
    float4 xv = reinterpret_cast<const float4*>(x)[i];
    int cg = (int)(i & 31);
    float4 sc = reinterpret_cast<const float4*>(g_scale)[cg];
    float4 sh = reinterpret_cast<const float4*>(g_shift)[cg];
    float4 r2;
    r2.x = fmaf(yv.x, sc.x, sh.x) + xv.x;
    r2.y = fmaf(yv.y, sc.y, sh.y) + xv.y;
    r2.z = fmaf(yv.z, sc.z, sh.z) + xv.z;
    r2.w = fmaf(yv.w, sc.w, sh.w) + xv.w;
    reinterpret_cast<float4*>(g_R)[i] = r2;
    reinterpret_cast<float4*>(g_T)[i] =
        make_float4(fmaxf(r2.x,0.f), fmaxf(r2.y,0.f), fmaxf(r2.z,0.f), fmaxf(r2.w,0.f));
}

// out = relu(BN2(y) + r2)
__global__ void ew2_kernel(const float* __restrict__ y, float* __restrict__ out)
{
    size_t i = (size_t)blockIdx.x * blockDim.x + threadIdx.x;
    float4 yv = reinterpret_cast<const float4*>(y)[i];
    float4 rv = reinterpret_cast<const float4*>(g_R)[i];
    int cg = (int)(i & 31);
    float4 sc = reinterpret_cast<const float4*>(g_scale)[cg];
    float4 sh = reinterpret_cast<const float4*>(g_shift)[cg];
    float4 o;
    o.x = fmaxf(fmaf(yv.x, sc.x, sh.x) + rv.x, 0.f);
    o.y = fmaxf(fmaf(yv.y, sc.y, sh.y) + rv.y, 0.f);
    o.z = fmaxf(fmaf(yv.z, sc.z, sh.z) + rv.z, 0.f);
    o.w = fmaxf(fmaf(yv.w, sc.w, sh.w) + rv.w, 0.f);
    reinterpret_cast<float4*>(out)[i] = o;
}

// ============================================================================
extern "C" void kernel_launch(void* const* d_in, const int* in_sizes, int n_in,
                              void* d_out, int out_size)
{
    const float* x      = (const float*)d_in[0];
    const float* Wa1    = (const float*)d_in[1];
    const float* Wv1    = (const float*)d_in[2];
    const float* W5     = (const float*)d_in[3];
    const float* W31    = (const float*)d_in[4];
    const float* W32    = (const float*)d_in[5];
    const float* gamma1 = (const float*)d_in[6];
    const float* beta1  = (const float*)d_in[7];
    const float* gamma2 = (const float*)d_in[8];
    const float* beta2  = (const float*)d_in[9];
    const int*   nbr5   = (const int*)d_in[10];
    const int*   nbr3a  = (const int*)d_in[11];
    const int*   nbr3b  = (const int*)d_in[12];
    float* out = (float*)d_out;

    float *pA, *pV, *pG, *pY, *pT;
    cudaGetSymbolAddress((void**)&pA, g_A);
    cudaGetSymbolAddress((void**)&pV, g_V);
    cudaGetSymbolAddress((void**)&pG, g_G);
    cudaGetSymbolAddress((void**)&pY, g_Y);
    cudaGetSymbolAddress((void**)&pT, g_T);

    cudaFuncSetAttribute(sconv_kernel,
                         cudaFuncAttributeMaxDynamicSharedMemorySize, SMEM_BYTES);

    const int grid = NPTS / TM;       // 256
    const int ewgrid = (NPTS*CH/4) / 256;

    // a = x @ Wa1 ; v = x @ Wv1
    sconv_kernel<<<grid, NT, SMEM_BYTES>>>(x, Wa1, nullptr, 1, nullptr, pA);
    sconv_kernel<<<grid, NT, SMEM_BYTES>>>(x, Wv1, nullptr, 1, nullptr, pV);
    // G = conv5(a) * v   (gate fused)
    sconv_kernel<<<grid, NT, SMEM_BYTES>>>(pA, W5, nbr5, 125, pV, pG);
    // y1 = conv3a(G); BN1; r2 = bn+x; T = relu(r2)
    sconv_kernel<<<grid, NT, SMEM_BYTES>>>(pG, W31, nbr3a, 27, nullptr, pY);
    bn_partial_kernel<<<64, 256>>>(pY);
    bn_finalize_kernel<<<1, 128>>>(gamma1, beta1);
    ew1_kernel<<<ewgrid, 256>>>(pY, x);
    // y2 = conv3b(T); BN2; out = relu(bn + r2)
    sconv_kernel<<<grid, NT, SMEM_BYTES>>>(pT, W32, nbr3b, 27, nullptr, pY);
    bn_partial_kernel<<<64, 256>>>(pY);
    bn_finalize_kernel<<<1, 128>>>(gamma2, beta2);
    ew2_kernel<<<ewgrid, 256>>>(pY, out);
}

// round 3
// speedup vs baseline: 3.1946x; 3.1946x over previous
#include <cuda_runtime.h>
#include <cuda_fp16.h>

#define NPTS 32768
#define CH   128
#define NT   256

// ======================= baseline-PTX helpers (compile at compute_103) ====
__device__ __forceinline__ unsigned smem_to_u32(const void* p) {
    unsigned a;
    asm("{ .reg .u64 t; cvta.to.shared.u64 t, %1; cvt.u32.u64 %0, t; }" : "=r"(a) : "l"(p));
    return a;
}
#define MBARRIER_INIT(mbar, cnt) \
    asm volatile("mbarrier.init.shared.b64 [%0], %1;" :: "r"((unsigned)(mbar)), "r"((unsigned)(cnt)) : "memory")
#define MBARRIER_ARRIVE_EXPECT_TX(mbar, bytes) \
    asm volatile("mbarrier.arrive.expect_tx.shared.b64 _, [%0], %1;" \
        :: "r"((unsigned)(mbar)), "r"((unsigned)(bytes)) : "memory")
#define MBARRIER_WAIT_PARITY(mbar, par) do { \
    unsigned _m = (unsigned)(mbar), _p = (unsigned)(par), _d; \
    asm volatile("{\n\t.reg .pred p;\n\t" \
        "mbarrier.try_wait.parity.acquire.cta.shared::cta.b64 p, [%1], %2;\n\t" \
        "selp.b32 %0, 1, 0, p;\n\t}" : "=r"(_d) : "r"(_m), "r"(_p) : "memory"); \
    if (!_d) { \
        asm volatile("{\n\t.reg .pred P1;\n\t" \
            "WL_%=:\n\t" \
            "mbarrier.try_wait.parity.acquire.cta.shared::cta.b64 P1, [%0], %1, 0x989680;\n\t" \
            "@P1 bra.uni WD_%=;\n\t" \
            "bra.uni WL_%=;\n\t" \
            "WD_%=:\n\t}" :: "r"(_m), "r"(_p) : "memory"); \
    } } while (0)
__device__ __forceinline__ void bulk_g2s(unsigned dst, const void* src, unsigned bytes, unsigned mbar) {
    asm volatile("cp.async.bulk.shared::cluster.global.mbarrier::complete_tx::bytes [%0], [%1], %2, [%3];"
        :: "r"(dst), "l"(src), "r"(bytes), "r"(mbar) : "memory");
}
#define FENCE_PROXY_ASYNC() asm volatile("fence.proxy.async.shared::cta;" ::: "memory")

__device__ __forceinline__ void ldsm_x4(unsigned* r, unsigned addr) {
    asm volatile("ldmatrix.sync.aligned.m8n8.x4.shared.b16 {%0,%1,%2,%3}, [%4];"
        : "=r"(r[0]), "=r"(r[1]), "=r"(r[2]), "=r"(r[3]) : "r"(addr));
}
__device__ __forceinline__ void ldsm_x4_t(unsigned* r, unsigned addr) {
    asm volatile("ldmatrix.sync.aligned.m8n8.x4.trans.shared.b16 {%0,%1,%2,%3}, [%4];"
        : "=r"(r[0]), "=r"(r[1]), "=r"(r[2]), "=r"(r[3]) : "r"(addr));
}
__device__ __forceinline__ void mma16816(float* c, const unsigned* a, unsigned b0, unsigned b1) {
    asm volatile("mma.sync.aligned.m16n8k16.row.col.f32.f16.f16.f32 "
        "{%0,%1,%2,%3}, {%4,%5,%6,%7}, {%8,%9}, {%0,%1,%2,%3};"
        : "+f"(c[0]), "+f"(c[1]), "+f"(c[2]), "+f"(c[3])
        : "r"(a[0]), "r"(a[1]), "r"(a[2]), "r"(a[3]), "r"(b0), "r"(b1));
}

// ======================= scratch =======================
// Weight images: [tap][split(2)][ci:128][co:136 padded] fp16
#define WROW   136
#define BSPL   (128*WROW*2)           // bytes per split image = 34816
#define BBUF   (2*BSPL)               // bytes per tap (hi+lo) = 69632
#define ABUF   (128*WROW*2)           // A tile bytes (128 rows x 272B) = 34816
#define TCONV_SMEM (2*BBUF + 2*ABUF)  // 208896

__device__ __align__(16) float  g_A [NPTS*CH];
__device__ __align__(16) float  g_V [NPTS*CH];
__device__ __align__(16) float  g_Y [NPTS*CH];
__device__ __align__(16) float  g_R [NPTS*CH];
__device__ __align__(16) __half g_Ah[NPTS*CH];
__device__ __align__(16) __half g_Gh[NPTS*CH];
__device__ __align__(16) __half g_Th[NPTS*CH];
__device__ __align__(16) __half g_W5b [125*2*128*WROW];
__device__ __align__(16) __half g_W31b[27*2*128*WROW];
__device__ __align__(16) __half g_W32b[27*2*128*WROW];
__device__ int g_nT5 [125*NPTS];
__device__ int g_nT3a[27*NPTS];
__device__ int g_nT3b[27*NPTS];
__device__ __align__(16) float g_part[2*64*256];
__device__ __align__(16) float g_scale[CH];
__device__ __align__(16) float g_shift[CH];

// ======================= prep kernels =======================
// W[k][ci][co] fp32 -> [k][split][ci][co pad 136] fp16 hi/lo
__global__ void wprep_kernel(const float* __restrict__ W, __half* __restrict__ Wb)
{
    int e = blockIdx.x * 256 + threadIdx.x;
    int k = e >> 14, r = e & 16383;
    int ci = r >> 7, co = r & 127;
    float w = W[e];
    __half h = __float2half_rn(w);
    __half l = __float2half_rn(w - __half2float(h));
    size_t base = (size_t)k * (2*128*WROW);
    Wb[base + ci*WROW + co]            = h;
    Wb[base + 128*WROW + ci*WROW + co] = l;
}

// nbr[N][K] -> nbrT[K][N]
__global__ void ntr_kernel(const int* __restrict__ nbr, int* __restrict__ nbrT, int K)
{
    __shared__ int t[32][33];
    int k0 = blockIdx.x * 32, i0 = blockIdx.y * 32;
    int tx = threadIdx.x & 31, ty = threadIdx.x >> 5;
#pragma unroll
    for (int r = 0; r < 32; r += 8) {
        int kk = k0 + tx;
        t[ty + r][tx] = (kk < K) ? nbr[(size_t)(i0 + ty + r) * K + kk] : 0;
    }
    __syncthreads();
#pragma unroll
    for (int r = 0; r < 32; r += 8) {
        int kk = k0 + ty + r;
        if (kk < K) nbrT[(size_t)kk * NPTS + i0 + tx] = t[tx][ty + r];
    }
}

__global__ void cvt_kernel(const float* __restrict__ in, __half* __restrict__ out)
{
    int i = blockIdx.x * 256 + threadIdx.x;       // float4 units
    float4 v = reinterpret_cast<const float4*>(in)[i];
    reinterpret_cast<__half2*>(out)[2*i]   = __floats2half2_rn(v.x, v.y);
    reinterpret_cast<__half2*>(out)[2*i+1] = __floats2half2_rn(v.z, v.w);
}

// ======================= HMMA gather-conv =======================
// out[i,:] = sum_k feats[nbrT[k,i],:] @ (Wh[k]+Wl[k]); optional fp32 gate mult.
// CTA: 128 rows x 128 cols, 8 warps, each warp M32 x N64.
__global__ void __launch_bounds__(NT, 1)
tconv_kernel(const __half* __restrict__ feats,
             const __half* __restrict__ Wb,     // [K][2][128][136] fp16
             const int*    __restrict__ nbrT,   // [K][NPTS]
             const int K,
             const float*  __restrict__ gate,   // fp32 or null
             __half* __restrict__ out16,        // or null
             float*  __restrict__ out32)        // or null
{
    extern __shared__ char dsm[];
    __shared__ __align__(8) unsigned long long s_mbar[2];

    const int tid  = threadIdx.x;
    const int lane = tid & 31;
    const int w    = tid >> 5;
    const int row0 = blockIdx.x * 128;
    const int m0   = (w >> 1) * 32;
    const int n0   = (w & 1) * 64;

    const unsigned smem = smem_to_u32(dsm);
    const unsigned mb   = smem_to_u32(&s_mbar[0]);

    if (tid == 0) { MBARRIER_INIT(mb, 129); MBARRIER_INIT(mb + 8, 129); }
    __syncthreads();

    // prologue: issue taps 0,1
#pragma unroll
    for (int t = 0; t < 2; ++t) {
        if (t < K) {
            unsigned bar = mb + 8u*t;
            if (tid < 128) {
                MBARRIER_ARRIVE_EXPECT_TX(bar, 256u);
                int idx = nbrT[(size_t)t * NPTS + row0 + tid];
                bulk_g2s(smem + 2*BBUF + (unsigned)t*ABUF + (unsigned)tid*(2*WROW),
                         feats + (size_t)idx * CH, 256u, bar);
            } else if (tid == 128) {
                MBARRIER_ARRIVE_EXPECT_TX(bar, (unsigned)BBUF);
                bulk_g2s(smem + (unsigned)t*BBUF, Wb + (size_t)t*(2*128*WROW),
                         (unsigned)BBUF, bar);
            }
        }
    }

    float acc[2][8][4];
#pragma unroll
    for (int i = 0; i < 2; ++i)
#pragma unroll
        for (int j = 0; j < 8; ++j)
#pragma unroll
            for (int e = 0; e < 4; ++e) acc[i][j][e] = 0.f;

    const unsigned lane_off = (unsigned)(lane & 15) * (2*WROW) + (unsigned)(lane >> 4) * 16u;

    for (int k = 0; k < K; ++k) {
        const unsigned buf = (unsigned)(k & 1);
        MBARRIER_WAIT_PARITY(mb + 8u*buf, (k >> 1) & 1);

        const unsigned Ab = smem + 2*BBUF + buf*ABUF;
        const unsigned Bb = smem + buf*BBUF;

#pragma unroll
        for (int ks = 0; ks < 8; ++ks) {
            unsigned a0[4], a1[4];
            unsigned abase = Ab + (unsigned)m0*(2*WROW) + (unsigned)ks*32u + lane_off;
            ldsm_x4(a0, abase);
            ldsm_x4(a1, abase + 16u*(2*WROW));
#pragma unroll
            for (int s = 0; s < 2; ++s) {
                unsigned bbase = Bb + (unsigned)s*BSPL + (unsigned)ks*16u*(2*WROW)
                               + (unsigned)n0*2u + lane_off;
                unsigned b[4][4];
#pragma unroll
                for (int p = 0; p < 4; ++p) ldsm_x4_t(b[p], bbase + (unsigned)p*32u);
#pragma unroll
                for (int p = 0; p < 4; ++p) {
                    mma16816(acc[0][2*p],   a0, b[p][0], b[p][1]);
                    mma16816(acc[0][2*p+1], a0, b[p][2], b[p][3]);
                    mma16816(acc[1][2*p],   a1, b[p][0], b[p][1]);
                    mma16816(acc[1][2*p+1], a1, b[p][2], b[p][3]);
                }
            }
        }

        FENCE_PROXY_ASYNC();
        __syncthreads();

        const int kn = k + 2;
        if (kn < K) {
            unsigned bar = mb + 8u*buf;
            if (tid < 128) {
                MBARRIER_ARRIVE_EXPECT_TX(bar, 256u);
                int idx = nbrT[(size_t)kn * NPTS + row0 + tid];
                bulk_g2s(Ab + (unsigned)tid*(2*WROW), feats + (size_t)idx * CH, 256u, bar);
            } else if (tid == 128) {
                MBARRIER_ARRIVE_EXPECT_TX(bar, (unsigned)BBUF);
                bulk_g2s(Bb, Wb + (size_t)kn*(2*128*WROW), (unsigned)BBUF, bar);
            }
        }
    }

    // epilogue
#pragma unroll
    for (int msub = 0; msub < 2; ++msub) {
#pragma unroll
        for (int nb = 0; nb < 8; ++nb) {
#pragma unroll
            for (int ep = 0; ep < 2; ++ep) {
                int row = row0 + m0 + msub*16 + (lane >> 2) + ep*8;
                int col = n0 + nb*8 + (lane & 3)*2;
                float v0 = acc[msub][nb][ep*2];
                float v1 = acc[msub][nb][ep*2 + 1];
                size_t off = (size_t)row * CH + col;
                if (gate) {
                    float2 g = *reinterpret_cast<const float2*>(gate + off);
                    v0 *= g.x; v1 *= g.y;
                }
                if (out32) *reinterpret_cast<float2*>(out32 + off) = make_float2(v0, v1);
                if (out16) *reinterpret_cast<__half2*>(out16 + off) = __floats2half2_rn(v0, v1);
            }
        }
    }
}

// ======================= SIMT 1x1 GEMM (exact fp32) =======================
#define TM 128
#define KC 32
#define SMEM_FLOATS (TM*CH + KC*CH + TM)
#define SMEM_BYTES  (SMEM_FLOATS * 4)
__global__ void __launch_bounds__(NT, 2)
sconv_kernel(const float* __restrict__ feats, const float* __restrict__ Wt,
             float* __restrict__ out)
{
    extern __shared__ float smem[];
    float* Fs = smem;
    float* Ws = smem + TM*CH;
    const int tid = threadIdx.x;
    const int row0 = blockIdx.x * TM;
    const int tcx = tid & 15, tcy = tid >> 4;
    float acc[8][8];
#pragma unroll
    for (int r = 0; r < 8; ++r)
#pragma unroll
        for (int c = 0; c < 8; ++c) acc[r][c] = 0.f;

#pragma unroll
    for (int j = 0; j < (TM*CH/4)/NT; ++j) {
        int lin = tid + j*NT;
        int r = lin >> 5, c4 = lin & 31;
        reinterpret_cast<float4*>(Fs + r*CH)[c4] =
            reinterpret_cast<const float4*>(feats + (size_t)(row0 + r)*CH)[c4];
    }
#pragma unroll 1
    for (int cc = 0; cc < CH/KC; ++cc) {
        __syncthreads();
#pragma unroll
        for (int j = 0; j < 4; ++j) {
            int lin = tid + j*NT;
            reinterpret_cast<float4*>(Ws)[lin] =
                reinterpret_cast<const float4*>(Wt + cc*(KC*CH))[lin];
        }
        __syncthreads();
        const float* fp = Fs + (tcy*8)*CH + cc*KC;
        const float4* wrow = reinterpret_cast<const float4*>(Ws);
#pragma unroll 4
        for (int ci = 0; ci < KC; ++ci) {
            float f[8];
#pragma unroll
            for (int r = 0; r < 8; ++r) f[r] = fp[r*CH + ci];
            float4 w0 = wrow[ci*(CH/4) + tcx*2];
            float4 w1 = wrow[ci*(CH/4) + tcx*2 + 1];
            float wv[8] = {w0.x, w0.y, w0.z, w0.w, w1.x, w1.y, w1.z, w1.w};
#pragma unroll
            for (int r = 0; r < 8; ++r)
#pragma unroll
                for (int c = 0; c < 8; ++c)
                    acc[r][c] = fmaf(f[r], wv[c], acc[r][c]);
        }
    }
#pragma unroll
    for (int r = 0; r < 8; ++r) {
        size_t base = (size_t)(row0 + tcy*8 + r)*CH + tcx*8;
        *reinterpret_cast<float4*>(out + base)     = make_float4(acc[r][0],acc[r][1],acc[r][2],acc[r][3]);
        *reinterpret_cast<float4*>(out + base + 4) = make_float4(acc[r][4],acc[r][5],acc[r][6],acc[r][7]);
    }
}

// ======================= BN / elementwise =======================
__global__ void bn_partial_kernel(const float* __restrict__ y)
{
    int tid = threadIdx.x;
    int c = tid & (CH-1), half = tid >> 7;
    int rbase = blockIdx.x * 512 + half;
    float s = 0.f, s2 = 0.f;
#pragma unroll 8
    for (int j = 0; j < 256; ++j) {
        float v = y[(size_t)(rbase + 2*j)*CH + c];
        s += v; s2 = fmaf(v, v, s2);
    }
    g_part[blockIdx.x*256 + tid]          = s;
    g_part[64*256 + blockIdx.x*256 + tid] = s2;
}
__global__ void bn_finalize_kernel(const float* __restrict__ gamma, const float* __restrict__ beta)
{
    int c = threadIdx.x;
    float s = 0.f, s2 = 0.f;
    for (int b = 0; b < 64; ++b) {
        s  += g_part[b*256 + c] + g_part[b*256 + CH + c];
        s2 += g_part[64*256 + b*256 + c] + g_part[64*256 + b*256 + CH + c];
    }
    const float inv = 1.0f / (float)NPTS;
    float mu = s * inv;
    float var = s2 * inv - mu*mu;
    float sc = gamma[c] * rsqrtf(var + 1e-5f);
    g_scale[c] = sc;
    g_shift[c] = fmaf(-mu, sc, beta[c]);
}
// R = BN1(y)+x ; Th = fp16(relu(R))
__global__ void ew1_kernel(const float* __restrict__ y, const float* __restrict__ x)
{
    size_t i = (size_t)blockIdx.x * blockDim.x + threadIdx.x;
    float4 yv = reinterpret_cast<const float4*>(y)[i];
    float4 xv = reinterpret_cast<const float4*>(x)[i];
    int cg = (int)(i & 31);
    float4 sc = reinterpret_cast<const float4*>(g_scale)[cg];
    float4 sh = reinterpret_cast<const float4*>(g_shift)[cg];
    float4 r2;
    r2.x = fmaf(yv.x, sc.x, sh.x) + xv.x;
    r2.y = fmaf(yv.y, sc.y, sh.y) + xv.y;
    r2.z = fmaf(yv.z, sc.z, sh.z) + xv.z;
    r2.w = fmaf(yv.w, sc.w, sh.w) + xv.w;
    reinterpret_cast<float4*>(g_R)[i] = r2;
    reinterpret_cast<__half2*>(g_Th)[2*i]   = __floats2half2_rn(fmaxf(r2.x,0.f), fmaxf(r2.y,0.f));
    reinterpret_cast<__half2*>(g_Th)[2*i+1] = __floats2half2_rn(fmaxf(r2.z,0.f), fmaxf(r2.w,0.f));
}
// out = relu(BN2(y) + R)
__global__ void ew2_kernel(const float* __restrict__ y, float* __restrict__ out)
{
    size_t i = (size_t)blockIdx.x * blockDim.x + threadIdx.x;
    float4 yv = reinterpret_cast<const float4*>(y)[i];
    float4 rv = reinterpret_cast<const float4*>(g_R)[i];
    int cg = (int)(i & 31);
    float4 sc = reinterpret_cast<const float4*>(g_scale)[cg];
    float4 sh = reinterpret_cast<const float4*>(g_shift)[cg];
    float4 o;
    o.x = fmaxf(fmaf(yv.x, sc.x, sh.x) + rv.x, 0.f);
    o.y = fmaxf(fmaf(yv.y, sc.y, sh.y) + rv.y, 0.f);
    o.z = fmaxf(fmaf(yv.z, sc.z, sh.z) + rv.z, 0.f);
    o.w = fmaxf(fmaf(yv.w, sc.w, sh.w) + rv.w, 0.f);
    reinterpret_cast<float4*>(out)[i] = o;
}

// ======================= launch =======================
extern "C" void kernel_launch(void* const* d_in, const int* in_sizes, int n_in,
                              void* d_out, int out_size)
{
    const float* x      = (const float*)d_in[0];
    const float* Wa1    = (const float*)d_in[1];
    const float* Wv1    = (const float*)d_in[2];
    const float* W5     = (const float*)d_in[3];
    const float* W31    = (const float*)d_in[4];
    const float* W32    = (const float*)d_in[5];
    const float* gamma1 = (const float*)d_in[6];
    const float* beta1  = (const float*)d_in[7];
    const float* gamma2 = (const float*)d_in[8];
    const float* beta2  = (const float*)d_in[9];
    const int*   nbr5   = (const int*)d_in[10];
    const int*   nbr3a  = (const int*)d_in[11];
    const int*   nbr3b  = (const int*)d_in[12];
    float* out = (float*)d_out;

    float *pA, *pV, *pY;
    __half *pAh, *pGh, *pTh, *pW5b, *pW31b, *pW32b;
    int *pn5, *pn3a, *pn3b;
    cudaGetSymbolAddress((void**)&pA,  g_A);
    cudaGetSymbolAddress((void**)&pV,  g_V);
    cudaGetSymbolAddress((void**)&pY,  g_Y);
    cudaGetSymbolAddress((void**)&pAh, g_Ah);
    cudaGetSymbolAddress((void**)&pGh, g_Gh);
    cudaGetSymbolAddress((void**)&pTh, g_Th);
    cudaGetSymbolAddress((void**)&pW5b, g_W5b);
    cudaGetSymbolAddress((void**)&pW31b, g_W31b);
    cudaGetSymbolAddress((void**)&pW32b, g_W32b);
    cudaGetSymbolAddress((void**)&pn5,  g_nT5);
    cudaGetSymbolAddress((void**)&pn3a, g_nT3a);
    cudaGetSymbolAddress((void**)&pn3b, g_nT3b);

    cudaFuncSetAttribute(sconv_kernel, cudaFuncAttributeMaxDynamicSharedMemorySize, SMEM_BYTES);
    cudaFuncSetAttribute(tconv_kernel, cudaFuncAttributeMaxDynamicSharedMemorySize, TCONV_SMEM);

    // --- prep: weight split+pad images, neighbor transposes ---
    wprep_kernel<<<125*64, 256>>>(W5,  pW5b);
    wprep_kernel<<<27*64, 256>>>(W31, pW31b);
    wprep_kernel<<<27*64, 256>>>(W32, pW32b);
    ntr_kernel<<<dim3(4, NPTS/32), 256>>>(nbr5,  pn5,  125);
    ntr_kernel<<<dim3(1, NPTS/32), 256>>>(nbr3a, pn3a, 27);
    ntr_kernel<<<dim3(1, NPTS/32), 256>>>(nbr3b, pn3b, 27);

    const int ggrid = NPTS / TM;          // 256
    const int tgrid = NPTS / 128;         // 256
    const int ewgrid = (NPTS*CH/4) / 256;

    // a = x @ Wa1 (fp32 -> fp16) ; v = x @ Wv1
    sconv_kernel<<<ggrid, NT, SMEM_BYTES>>>(x, Wa1, pA);
    cvt_kernel<<<ewgrid, 256>>>(pA, pAh);
    sconv_kernel<<<ggrid, NT, SMEM_BYTES>>>(x, Wv1, pV);
    // Gh = fp16( conv5(a) * v )
    tconv_kernel<<<tgrid, NT, TCONV_SMEM>>>(pAh, pW5b, pn5, 125, pV, pGh, nullptr);
    // Y = conv3a(G); BN1; R = bn+x; Th = fp16(relu(R))
    tconv_kernel<<<tgrid, NT, TCONV_SMEM>>>(pGh, pW31b, pn3a, 27, nullptr, nullptr, pY);
    bn_partial_kernel<<<64, 256>>>(pY);
    bn_finalize_kernel<<<1, 128>>>(gamma1, beta1);
    ew1_kernel<<<ewgrid, 256>>>(pY, x);
    // Y = conv3b(T); BN2; out = relu(bn + R)
    tconv_kernel<<<tgrid, NT, TCONV_SMEM>>>(pTh, pW32b, pn3b, 27, nullptr, nullptr, pY);
    bn_partial_kernel<<<64, 256>>>(pY);
    bn_finalize_kernel<<<1, 128>>>(gamma2, beta2);
    ew2_kernel<<<ewgrid, 256>>>(pY, out);
}

// round 4
// speedup vs baseline: 6.1629x; 1.9292x over previous
#include <cuda_runtime.h>
#include <cuda_fp16.h>

#define NPTS 32768
#define CH   128
#define NT   256

// ======================= baseline-PTX helpers (compile at compute_103) ====
__device__ __forceinline__ unsigned smem_to_u32(const void* p) {
    unsigned a;
    asm("{ .reg .u64 t; cvta.to.shared.u64 t, %1; cvt.u32.u64 %0, t; }" : "=r"(a) : "l"(p));
    return a;
}
#define MBARRIER_INIT(mbar, cnt) \
    asm volatile("mbarrier.init.shared.b64 [%0], %1;" :: "r"((unsigned)(mbar)), "r"((unsigned)(cnt)) : "memory")
#define MBARRIER_ARRIVE_EXPECT_TX(mbar, bytes) \
    asm volatile("mbarrier.arrive.expect_tx.shared.b64 _, [%0], %1;" \
        :: "r"((unsigned)(mbar)), "r"((unsigned)(bytes)) : "memory")
#define MBARRIER_WAIT_PARITY(mbar, par) do { \
    unsigned _m = (unsigned)(mbar), _p = (unsigned)(par), _d; \
    asm volatile("{\n\t.reg .pred p;\n\t" \
        "mbarrier.try_wait.parity.acquire.cta.shared::cta.b64 p, [%1], %2;\n\t" \
        "selp.b32 %0, 1, 0, p;\n\t}" : "=r"(_d) : "r"(_m), "r"(_p) : "memory"); \
    if (!_d) { \
        asm volatile("{\n\t.reg .pred P1;\n\t" \
            "WL_%=:\n\t" \
            "mbarrier.try_wait.parity.acquire.cta.shared::cta.b64 P1, [%0], %1, 0x989680;\n\t" \
            "@P1 bra.uni WD_%=;\n\t" \
            "bra.uni WL_%=;\n\t" \
            "WD_%=:\n\t}" :: "r"(_m), "r"(_p) : "memory"); \
    } } while (0)
__device__ __forceinline__ void bulk_g2s(unsigned dst, const void* src, unsigned bytes, unsigned mbar) {
    asm volatile("cp.async.bulk.shared::cluster.global.mbarrier::complete_tx::bytes [%0], [%1], %2, [%3];"
        :: "r"(dst), "l"(src), "r"(bytes), "r"(mbar) : "memory");
}
#define FENCE_PROXY_ASYNC() asm volatile("fence.proxy.async.shared::cta;" ::: "memory")

__device__ __forceinline__ void ldsm_x4(unsigned* r, unsigned addr) {
    asm volatile("ldmatrix.sync.aligned.m8n8.x4.shared.b16 {%0,%1,%2,%3}, [%4];"
        : "=r"(r[0]), "=r"(r[1]), "=r"(r[2]), "=r"(r[3]) : "r"(addr));
}
__device__ __forceinline__ void ldsm_x4_t(unsigned* r, unsigned addr) {
    asm volatile("ldmatrix.sync.aligned.m8n8.x4.trans.shared.b16 {%0,%1,%2,%3}, [%4];"
        : "=r"(r[0]), "=r"(r[1]), "=r"(r[2]), "=r"(r[3]) : "r"(addr));
}
__device__ __forceinline__ void mma16816(float* c, const unsigned* a, unsigned b0, unsigned b1) {
    asm volatile("mma.sync.aligned.m16n8k16.row.col.f32.f16.f16.f32 "
        "{%0,%1,%2,%3}, {%4,%5,%6,%7}, {%8,%9}, {%0,%1,%2,%3};"
        : "+f"(c[0]), "+f"(c[1]), "+f"(c[2]), "+f"(c[3])
        : "r"(a[0]), "r"(a[1]), "r"(a[2]), "r"(a[3]), "r"(b0), "r"(b1));
}

// ======================= sizes =======================
// Weight image: [tap][ci:128][co:136 padded] fp16 (single precision level)
#define WROW   136
#define BBUF   (128*WROW*2)           // bytes per tap = 34816
#define ABUF   (128*WROW*2)           // A tile bytes (128 rows x 272B) = 34816
#define TCONV_SMEM (2*BBUF + 2*ABUF)  // 139264

// ======================= scratch =======================
__device__ __align__(16) float  g_V [NPTS*CH];
__device__ __align__(16) float  g_Y [NPTS*CH];
__device__ __align__(16) float  g_R [NPTS*CH];
__device__ __align__(16) __half g_Ah[NPTS*CH];
__device__ __align__(16) __half g_Gh[NPTS*CH];
__device__ __align__(16) __half g_Th[NPTS*CH];
__device__ __align__(16) __half g_W5b [125*128*WROW];
__device__ __align__(16) __half g_W31b[27*128*WROW];
__device__ __align__(16) __half g_W32b[27*128*WROW];
__device__ int g_nT5 [125*NPTS];
__device__ int g_nT3a[27*NPTS];
__device__ int g_nT3b[27*NPTS];
__device__ __align__(16) float g_part[2*64*256];
__device__ __align__(16) float g_scale[CH];
__device__ __align__(16) float g_shift[CH];

// ======================= prep kernels =======================
// W[k][ci][co] fp32 -> [k][ci][co pad 136] fp16
__global__ void wprep_kernel(const float* __restrict__ W, __half* __restrict__ Wb)
{
    int e = blockIdx.x * 256 + threadIdx.x;
    int k = e >> 14, r = e & 16383;
    int ci = r >> 7, co = r & 127;
    Wb[(size_t)k * (128*WROW) + ci*WROW + co] = __float2half_rn(W[e]);
}

// nbr[N][K] -> nbrT[K][N]
__global__ void ntr_kernel(const int* __restrict__ nbr, int* __restrict__ nbrT, int K)
{
    __shared__ int t[32][33];
    int k0 = blockIdx.x * 32, i0 = blockIdx.y * 32;
    int tx = threadIdx.x & 31, ty = threadIdx.x >> 5;
#pragma unroll
    for (int r = 0; r < 32; r += 8) {
        int kk = k0 + tx;
        t[ty + r][tx] = (kk < K) ? nbr[(size_t)(i0 + ty + r) * K + kk] : 0;
    }
    __syncthreads();
#pragma unroll
    for (int r = 0; r < 32; r += 8) {
        int kk = k0 + ty + r;
        if (kk < K) nbrT[(size_t)kk * NPTS + i0 + tx] = t[tx][ty + r];
    }
}

// ======================= HMMA gather-conv =======================
// out[i,:] = sum_k feats[nbrT[k,i],:] @ W[k]; optional fp32 gate mult.
// CTA: 128 rows x 128 cols, 8 warps, each warp M32 x N64.
__global__ void __launch_bounds__(NT, 1)
tconv_kernel(const __half* __restrict__ feats,
             const __half* __restrict__ Wb,     // [K][128][136] fp16
             const int*    __restrict__ nbrT,   // [K][NPTS]
             const int K,
             const float*  __restrict__ gate,   // fp32 or null
             __half* __restrict__ out16,        // or null
             float*  __restrict__ out32)        // or null
{
    extern __shared__ char dsm[];
    __shared__ __align__(8) unsigned long long s_mbar[2];

    const int tid  = threadIdx.x;
    const int lane = tid & 31;
    const int w    = tid >> 5;
    const int row0 = blockIdx.x * 128;
    const int m0   = (w >> 1) * 32;
    const int n0   = (w & 1) * 64;

    const unsigned smem = smem_to_u32(dsm);
    const unsigned mb   = smem_to_u32(&s_mbar[0]);

    if (tid == 0) { MBARRIER_INIT(mb, 129); MBARRIER_INIT(mb + 8, 129); }
    __syncthreads();

    // prologue: issue taps 0,1
#pragma unroll
    for (int t = 0; t < 2; ++t) {
        if (t < K) {
            unsigned bar = mb + 8u*t;
            if (tid < 128) {
                MBARRIER_ARRIVE_EXPECT_TX(bar, 256u);
                int idx = nbrT[(size_t)t * NPTS + row0 + tid];
                bulk_g2s(smem + 2*BBUF + (unsigned)t*ABUF + (unsigned)tid*(2*WROW),
                         feats + (size_t)idx * CH, 256u, bar);
            } else if (tid == 128) {
                MBARRIER_ARRIVE_EXPECT_TX(bar, (unsigned)BBUF);
                bulk_g2s(smem + (unsigned)t*BBUF, Wb + (size_t)t*(128*WROW),
                         (unsigned)BBUF, bar);
            }
        }
    }

    float acc[2][8][4];
#pragma unroll
    for (int i = 0; i < 2; ++i)
#pragma unroll
        for (int j = 0; j < 8; ++j)
#pragma unroll
            for (int e = 0; e < 4; ++e) acc[i][j][e] = 0.f;

    const unsigned lane_off = (unsigned)(lane & 15) * (2*WROW) + (unsigned)(lane >> 4) * 16u;

    for (int k = 0; k < K; ++k) {
        const unsigned buf = (unsigned)(k & 1);
        MBARRIER_WAIT_PARITY(mb + 8u*buf, (k >> 1) & 1);

        const unsigned Ab = smem + 2*BBUF + buf*ABUF;
        const unsigned Bb = smem + buf*BBUF;

#pragma unroll
        for (int ks = 0; ks < 8; ++ks) {
            unsigned a0[4], a1[4];
            unsigned abase = Ab + (unsigned)m0*(2*WROW) + (unsigned)ks*32u + lane_off;
            ldsm_x4(a0, abase);
            ldsm_x4(a1, abase + 16u*(2*WROW));
            unsigned bbase = Bb + (unsigned)ks*16u*(2*WROW) + (unsigned)n0*2u + lane_off;
            unsigned b[4][4];
#pragma unroll
            for (int p = 0; p < 4; ++p) ldsm_x4_t(b[p], bbase + (unsigned)p*32u);
#pragma unroll
            for (int p = 0; p < 4; ++p) {
                mma16816(acc[0][2*p],   a0, b[p][0], b[p][1]);
                mma16816(acc[0][2*p+1], a0, b[p][2], b[p][3]);
                mma16816(acc[1][2*p],   a1, b[p][0], b[p][1]);
                mma16816(acc[1][2*p+1], a1, b[p][2], b[p][3]);
            }
        }

        FENCE_PROXY_ASYNC();
        __syncthreads();

        const int kn = k + 2;
        if (kn < K) {
            unsigned bar = mb + 8u*buf;
            if (tid < 128) {
                MBARRIER_ARRIVE_EXPECT_TX(bar, 256u);
                int idx = nbrT[(size_t)kn * NPTS + row0 + tid];
                bulk_g2s(Ab + (unsigned)tid*(2*WROW), feats + (size_t)idx * CH, 256u, bar);
            } else if (tid == 128) {
                MBARRIER_ARRIVE_EXPECT_TX(bar, (unsigned)BBUF);
                bulk_g2s(Bb, Wb + (size_t)kn*(128*WROW), (unsigned)BBUF, bar);
            }
        }
    }

    // epilogue
#pragma unroll
    for (int msub = 0; msub < 2; ++msub) {
#pragma unroll
        for (int nb = 0; nb < 8; ++nb) {
#pragma unroll
            for (int ep = 0; ep < 2; ++ep) {
                int row = row0 + m0 + msub*16 + (lane >> 2) + ep*8;
                int col = n0 + nb*8 + (lane & 3)*2;
                float v0 = acc[msub][nb][ep*2];
                float v1 = acc[msub][nb][ep*2 + 1];
                size_t off = (size_t)row * CH + col;
                if (gate) {
                    float2 g = *reinterpret_cast<const float2*>(gate + off);
                    v0 *= g.x; v1 *= g.y;
                }
                if (out32) *reinterpret_cast<float2*>(out32 + off) = make_float2(v0, v1);
                if (out16) *reinterpret_cast<__half2*>(out16 + off) = __floats2half2_rn(v0, v1);
            }
        }
    }
}

// ======================= SIMT 1x1 GEMM (exact fp32, fused fp16 out) =========
#define TM 128
#define KC 32
#define SMEM_FLOATS (TM*CH + KC*CH + TM)
#define SMEM_BYTES  (SMEM_FLOATS * 4)
__global__ void __launch_bounds__(NT, 2)
sconv_kernel(const float* __restrict__ feats, const float* __restrict__ Wt,
             float* __restrict__ out32, __half* __restrict__ out16)
{
    extern __shared__ float smem[];
    float* Fs = smem;
    float* Ws = smem + TM*CH;
    const int tid = threadIdx.x;
    const int row0 = blockIdx.x * TM;
    const int tcx = tid & 15, tcy = tid >> 4;
    float acc[8][8];
#pragma unroll
    for (int r = 0; r < 8; ++r)
#pragma unroll
        for (int c = 0; c < 8; ++c) acc[r][c] = 0.f;

#pragma unroll
    for (int j = 0; j < (TM*CH/4)/NT; ++j) {
        int lin = tid + j*NT;
        int r = lin >> 5, c4 = lin & 31;
        reinterpret_cast<float4*>(Fs + r*CH)[c4] =
            reinterpret_cast<const float4*>(feats + (size_t)(row0 + r)*CH)[c4];
    }
#pragma unroll 1
    for (int cc = 0; cc < CH/KC; ++cc) {
        __syncthreads();
#pragma unroll
        for (int j = 0; j < 4; ++j) {
            int lin = tid + j*NT;
            reinterpret_cast<float4*>(Ws)[lin] =
                reinterpret_cast<const float4*>(Wt + cc*(KC*CH))[lin];
        }
        __syncthreads();
        const float* fp = Fs + (tcy*8)*CH + cc*KC;
        const float4* wrow = reinterpret_cast<const float4*>(Ws);
#pragma unroll 4
        for (int ci = 0; ci < KC; ++ci) {
            float f[8];
#pragma unroll
            for (int r = 0; r < 8; ++r) f[r] = fp[r*CH + ci];
            float4 w0 = wrow[ci*(CH/4) + tcx*2];
            float4 w1 = wrow[ci*(CH/4) + tcx*2 + 1];
            float wv[8] = {w0.x, w0.y, w0.z, w0.w, w1.x, w1.y, w1.z, w1.w};
#pragma unroll
            for (int r = 0; r < 8; ++r)
#pragma unroll
                for (int c = 0; c < 8; ++c)
                    acc[r][c] = fmaf(f[r], wv[c], acc[r][c]);
        }
    }
#pragma unroll
    for (int r = 0; r < 8; ++r) {
        size_t base = (size_t)(row0 + tcy*8 + r)*CH + tcx*8;
        if (out32) {
            *reinterpret_cast<float4*>(out32 + base)     = make_float4(acc[r][0],acc[r][1],acc[r][2],acc[r][3]);
            *reinterpret_cast<float4*>(out32 + base + 4) = make_float4(acc[r][4],acc[r][5],acc[r][6],acc[r][7]);
        }
        if (out16) {
            __half2* hp = reinterpret_cast<__half2*>(out16 + base);
            hp[0] = __floats2half2_rn(acc[r][0], acc[r][1]);
            hp[1] = __floats2half2_rn(acc[r][2], acc[r][3]);
            hp[2] = __floats2half2_rn(acc[r][4], acc[r][5]);
            hp[3] = __floats2half2_rn(acc[r][6], acc[r][7]);
        }
    }
}

// ======================= BN / elementwise =======================
__global__ void bn_partial_kernel(const float* __restrict__ y)
{
    int tid = threadIdx.x;
    int c = tid & (CH-1), half = tid >> 7;
    int rbase = blockIdx.x * 512 + half;
    float s = 0.f, s2 = 0.f;
#pragma unroll 8
    for (int j = 0; j < 256; ++j) {
        float v = y[(size_t)(rbase + 2*j)*CH + c];
        s += v; s2 = fmaf(v, v, s2);
    }
    g_part[blockIdx.x*256 + tid]          = s;
    g_part[64*256 + blockIdx.x*256 + tid] = s2;
}
__global__ void bn_finalize_kernel(const float* __restrict__ gamma, const float* __restrict__ beta)
{
    int c = threadIdx.x;
    float s = 0.f, s2 = 0.f;
    for (int b = 0; b < 64; ++b) {
        s  += g_part[b*256 + c] + g_part[b*256 + CH + c];
        s2 += g_part[64*256 + b*256 + c] + g_part[64*256 + b*256 + CH + c];
    }
    const float inv = 1.0f / (float)NPTS;
    float mu = s * inv;
    float var = s2 * inv - mu*mu;
    float sc = gamma[c] * rsqrtf(var + 1e-5f);
    g_scale[c] = sc;
    g_shift[c] = fmaf(-mu, sc, beta[c]);
}
// R = BN1(y)+x ; Th = fp16(relu(R))
__global__ void ew1_kernel(const float* __restrict__ y, const float* __restrict__ x)
{
    size_t i = (size_t)blockIdx.x * blockDim.x + threadIdx.x;
    float4 yv = reinterpret_cast<const float4*>(y)[i];
    float4 xv = reinterpret_cast<const float4*>(x)[i];
    int cg = (int)(i & 31);
    float4 sc = reinterpret_cast<const float4*>(g_scale)[cg];
    float4 sh = reinterpret_cast<const float4*>(g_shift)[cg];
    float4 r2;
    r2.x = fmaf(yv.x, sc.x, sh.x) + xv.x;
    r2.y = fmaf(yv.y, sc.y, sh.y) + xv.y;
    r2.z = fmaf(yv.z, sc.z, sh.z) + xv.z;
    r2.w = fmaf(yv.w, sc.w, sh.w) + xv.w;
    reinterpret_cast<float4*>(g_R)[i] = r2;
    reinterpret_cast<__half2*>(g_Th)[2*i]   = __floats2half2_rn(fmaxf(r2.x,0.f), fmaxf(r2.y,0.f));
    reinterpret_cast<__half2*>(g_Th)[2*i+1] = __floats2half2_rn(fmaxf(r2.z,0.f), fmaxf(r2.w,0.f));
}
// out = relu(BN2(y) + R)
__global__ void ew2_kernel(const float* __restrict__ y, float* __restrict__ out)
{
    size_t i = (size_t)blockIdx.x * blockDim.x + threadIdx.x;
    float4 yv = reinterpret_cast<const float4*>(y)[i];
    float4 rv = reinterpret_cast<const float4*>(g_R)[i];
    int cg = (int)(i & 31);
    float4 sc = reinterpret_cast<const float4*>(g_scale)[cg];
    float4 sh = reinterpret_cast<const float4*>(g_shift)[cg];
    float4 o;
    o.x = fmaxf(fmaf(yv.x, sc.x, sh.x) + rv.x, 0.f);
    o.y = fmaxf(fmaf(yv.y, sc.y, sh.y) + rv.y, 0.f);
    o.z = fmaxf(fmaf(yv.z, sc.z, sh.z) + rv.z, 0.f);
    o.w = fmaxf(fmaf(yv.w, sc.w, sh.w) + rv.w, 0.f);
    reinterpret_cast<float4*>(out)[i] = o;
}

// ======================= launch =======================
extern "C" void kernel_launch(void* const* d_in, const int* in_sizes, int n_in,
                              void* d_out, int out_size)
{
    const float* x      = (const float*)d_in[0];
    const float* Wa1    = (const float*)d_in[1];
    const float* Wv1    = (const float*)d_in[2];
    const float* W5     = (const float*)d_in[3];
    const float* W31    = (const float*)d_in[4];
    const float* W32    = (const float*)d_in[5];
    const float* gamma1 = (const float*)d_in[6];
    const float* beta1  = (const float*)d_in[7];
    const float* gamma2 = (const float*)d_in[8];
    const float* beta2  = (const float*)d_in[9];
    const int*   nbr5   = (const int*)d_in[10];
    const int*   nbr3a  = (const int*)d_in[11];
    const int*   nbr3b  = (const int*)d_in[12];
    float* out = (float*)d_out;

    float *pV, *pY;
    __half *pAh, *pGh, *pTh, *pW5b, *pW31b, *pW32b;
    int *pn5, *pn3a, *pn3b;
    cudaGetSymbolAddress((void**)&pV,  g_V);
    cudaGetSymbolAddress((void**)&pY,  g_Y);
    cudaGetSymbolAddress((void**)&pAh, g_Ah);
    cudaGetSymbolAddress((void**)&pGh, g_Gh);
    cudaGetSymbolAddress((void**)&pTh, g_Th);
    cudaGetSymbolAddress((void**)&pW5b, g_W5b);
    cudaGetSymbolAddress((void**)&pW31b, g_W31b);
    cudaGetSymbolAddress((void**)&pW32b, g_W32b);
    cudaGetSymbolAddress((void**)&pn5,  g_nT5);
    cudaGetSymbolAddress((void**)&pn3a, g_nT3a);
    cudaGetSymbolAddress((void**)&pn3b, g_nT3b);

    cudaFuncSetAttribute(sconv_kernel, cudaFuncAttributeMaxDynamicSharedMemorySize, SMEM_BYTES);
    cudaFuncSetAttribute(tconv_kernel, cudaFuncAttributeMaxDynamicSharedMemorySize, TCONV_SMEM);

    // --- prep: weight images, neighbor transposes ---
    wprep_kernel<<<125*64, 256>>>(W5,  pW5b);
    wprep_kernel<<<27*64, 256>>>(W31, pW31b);
    wprep_kernel<<<27*64, 256>>>(W32, pW32b);
    ntr_kernel<<<dim3(4, NPTS/32), 256>>>(nbr5,  pn5,  125);
    ntr_kernel<<<dim3(1, NPTS/32), 256>>>(nbr3a, pn3a, 27);
    ntr_kernel<<<dim3(1, NPTS/32), 256>>>(nbr3b, pn3b, 27);

    const int ggrid = NPTS / TM;          // 256
    const int tgrid = NPTS / 128;         // 256
    const int ewgrid = (NPTS*CH/4) / 256;

    // a = fp16(x @ Wa1) ; v = x @ Wv1 (fp32 gate)
    sconv_kernel<<<ggrid, NT, SMEM_BYTES>>>(x, Wa1, nullptr, pAh);
    sconv_kernel<<<ggrid, NT, SMEM_BYTES>>>(x, Wv1, pV, nullptr);
    // Gh = fp16( conv5(a) * v )
    tconv_kernel<<<tgrid, NT, TCONV_SMEM>>>(pAh, pW5b, pn5, 125, pV, pGh, nullptr);
    // Y = conv3a(G); BN1; R = bn+x; Th = fp16(relu(R))
    tconv_kernel<<<tgrid, NT, TCONV_SMEM>>>(pGh, pW31b, pn3a, 27, nullptr, nullptr, pY);
    bn_partial_kernel<<<64, 256>>>(pY);
    bn_finalize_kernel<<<1, 128>>>(gamma1, beta1);
    ew1_kernel<<<ewgrid, 256>>>(pY, x);
    // Y = conv3b(T); BN2; out = relu(bn + R)
    tconv_kernel<<<tgrid, NT, TCONV_SMEM>>>(pTh, pW32b, pn3b, 27, nullptr, nullptr, pY);
    bn_partial_kernel<<<64, 256>>>(pY);
    bn_finalize_kernel<<<1, 128>>>(gamma2, beta2);
    ew2_kernel<<<ewgrid, 256>>>(pY, out);
}

// round 5
// speedup vs baseline: 6.6973x; 1.0867x over previous
#include <cuda_runtime.h>
#include <cuda_fp16.h>

#define NPTS 32768
#define CH   128
#define NT   256

// ======================= baseline-PTX helpers (compile at compute_103) ====
__device__ __forceinline__ unsigned smem_to_u32(const void* p) {
    unsigned a;
    asm("{ .reg .u64 t; cvta.to.shared.u64 t, %1; cvt.u32.u64 %0, t; }" : "=r"(a) : "l"(p));
    return a;
}
#define MBARRIER_INIT(mbar, cnt) \
    asm volatile("mbarrier.init.shared.b64 [%0], %1;" :: "r"((unsigned)(mbar)), "r"((unsigned)(cnt)) : "memory")
#define MBARRIER_ARRIVE_EXPECT_TX(mbar, bytes) \
    asm volatile("mbarrier.arrive.expect_tx.shared.b64 _, [%0], %1;" \
        :: "r"((unsigned)(mbar)), "r"((unsigned)(bytes)) : "memory")
#define MBARRIER_WAIT_PARITY(mbar, par) do { \
    unsigned _m = (unsigned)(mbar), _p = (unsigned)(par), _d; \
    asm volatile("{\n\t.reg .pred p;\n\t" \
        "mbarrier.try_wait.parity.acquire.cta.shared::cta.b64 p, [%1], %2;\n\t" \
        "selp.b32 %0, 1, 0, p;\n\t}" : "=r"(_d) : "r"(_m), "r"(_p) : "memory"); \
    if (!_d) { \
        asm volatile("{\n\t.reg .pred P1;\n\t" \
            "WL_%=:\n\t" \
            "mbarrier.try_wait.parity.acquire.cta.shared::cta.b64 P1, [%0], %1, 0x989680;\n\t" \
            "@P1 bra.uni WD_%=;\n\t" \
            "bra.uni WL_%=;\n\t" \
            "WD_%=:\n\t}" :: "r"(_m), "r"(_p) : "memory"); \
    } } while (0)
__device__ __forceinline__ void bulk_g2s(unsigned dst, const void* src, unsigned bytes, unsigned mbar) {
    asm volatile("cp.async.bulk.shared::cluster.global.mbarrier::complete_tx::bytes [%0], [%1], %2, [%3];"
        :: "r"(dst), "l"(src), "r"(bytes), "r"(mbar) : "memory");
}
#define FENCE_PROXY_ASYNC() asm volatile("fence.proxy.async.shared::cta;" ::: "memory")

__device__ __forceinline__ void ldsm_x4(unsigned* r, unsigned addr) {
    asm volatile("ldmatrix.sync.aligned.m8n8.x4.shared.b16 {%0,%1,%2,%3}, [%4];"
        : "=r"(r[0]), "=r"(r[1]), "=r"(r[2]), "=r"(r[3]) : "r"(addr));
}
__device__ __forceinline__ void ldsm_x4_t(unsigned* r, unsigned addr) {
    asm volatile("ldmatrix.sync.aligned.m8n8.x4.trans.shared.b16 {%0,%1,%2,%3}, [%4];"
        : "=r"(r[0]), "=r"(r[1]), "=r"(r[2]), "=r"(r[3]) : "r"(addr));
}
__device__ __forceinline__ void mma16816(float* c, const unsigned* a, unsigned b0, unsigned b1) {
    asm volatile("mma.sync.aligned.m16n8k16.row.col.f32.f16.f16.f32 "
        "{%0,%1,%2,%3}, {%4,%5,%6,%7}, {%8,%9}, {%0,%1,%2,%3};"
        : "+f"(c[0]), "+f"(c[1]), "+f"(c[2]), "+f"(c[3])
        : "r"(a[0]), "r"(a[1]), "r"(a[2]), "r"(a[3]), "r"(b0), "r"(b1));
}

// ======================= sizes =======================
// Weight image: [tap][ci:128][co:136 padded] fp16
#define WROW   136
#define BBUF   (128*WROW*2)            // bytes per tap B = 34816
#define MROWS  256                      // rows per CTA
#define ABUF   (MROWS*WROW*2)           // A tile bytes (256 rows x 272B) = 69632
#define TCONV_SMEM (2*BBUF + 2*ABUF)    // 208896

// ======================= scratch =======================
__device__ __align__(16) float  g_V [NPTS*CH];
__device__ __align__(16) float  g_Y [NPTS*CH];
__device__ __align__(16) float  g_R [NPTS*CH];
__device__ __align__(16) __half g_Ah[NPTS*CH];
__device__ __align__(16) __half g_Gh[NPTS*CH];
__device__ __align__(16) __half g_Th[NPTS*CH];
__device__ __align__(16) __half g_W5b [125*128*WROW];
__device__ __align__(16) __half g_W31b[27*128*WROW];
__device__ __align__(16) __half g_W32b[27*128*WROW];
__device__ int g_nT5 [125*NPTS];
__device__ int g_nT3a[27*NPTS];
__device__ int g_nT3b[27*NPTS];
__device__ __align__(16) float g_part[2*64*256];
__device__ __align__(16) float g_scale[CH];
__device__ __align__(16) float g_shift[CH];

// ======================= prep kernels =======================
__global__ void wprep_kernel(const float* __restrict__ W, __half* __restrict__ Wb)
{
    int e = blockIdx.x * 256 + threadIdx.x;
    int k = e >> 14, r = e & 16383;
    int ci = r >> 7, co = r & 127;
    Wb[(size_t)k * (128*WROW) + ci*WROW + co] = __float2half_rn(W[e]);
}

__global__ void ntr_kernel(const int* __restrict__ nbr, int* __restrict__ nbrT, int K)
{
    __shared__ int t[32][33];
    int k0 = blockIdx.x * 32, i0 = blockIdx.y * 32;
    int tx = threadIdx.x & 31, ty = threadIdx.x >> 5;
#pragma unroll
    for (int r = 0; r < 32; r += 8) {
        int kk = k0 + tx;
        t[ty + r][tx] = (kk < K) ? nbr[(size_t)(i0 + ty + r) * K + kk] : 0;
    }
    __syncthreads();
#pragma unroll
    for (int r = 0; r < 32; r += 8) {
        int kk = k0 + ty + r;
        if (kk < K) nbrT[(size_t)kk * NPTS + i0 + tx] = t[tx][ty + r];
    }
}

// ======================= HMMA gather-conv (M=256 tile) =======================
// out[i,:] = sum_k feats[nbrT[k,i],:] @ W[k]; optional fp32 gate mult.
// CTA: 256 rows x 128 cols, 8 warps = 4(m) x 2(n), each warp M64 x N64.
__global__ void __launch_bounds__(NT, 1)
tconv_kernel(const __half* __restrict__ feats,
             const __half* __restrict__ Wb,     // [K][128][136] fp16
             const int*    __restrict__ nbrT,   // [K][NPTS]
             const int K,
             const float*  __restrict__ gate,   // fp32 or null
             __half* __restrict__ out16,        // or null
             float*  __restrict__ out32)        // or null
{
    extern __shared__ char dsm[];
    __shared__ __align__(8) unsigned long long s_mbar[2];

    const int tid  = threadIdx.x;
    const int lane = tid & 31;
    const int w    = tid >> 5;
    const int row0 = blockIdx.x * MROWS;
    const int m0   = (w >> 1) * 64;
    const int n0   = (w & 1) * 64;

    const unsigned smem = smem_to_u32(dsm);
    const unsigned mb   = smem_to_u32(&s_mbar[0]);

    if (tid == 0) { MBARRIER_INIT(mb, 257); MBARRIER_INIT(mb + 8, 257); }
    __syncthreads();

    // prologue: issue taps 0,1 (every thread gathers one A row; tid 0 also B)
#pragma unroll
    for (int t = 0; t < 2; ++t) {
        unsigned bar = mb + 8u*t;
        MBARRIER_ARRIVE_EXPECT_TX(bar, 256u);
        int idx = nbrT[(size_t)t * NPTS + row0 + tid];
        bulk_g2s(smem + 2*BBUF + (unsigned)t*ABUF + (unsigned)tid*(2*WROW),
                 feats + (size_t)idx * CH, 256u, bar);
        if (tid == 0) {
            MBARRIER_ARRIVE_EXPECT_TX(bar, (unsigned)BBUF);
            bulk_g2s(smem + (unsigned)t*BBUF, Wb + (size_t)t*(128*WROW),
                     (unsigned)BBUF, bar);
        }
    }

    float acc[4][8][4];
#pragma unroll
    for (int i = 0; i < 4; ++i)
#pragma unroll
        for (int j = 0; j < 8; ++j)
#pragma unroll
            for (int e = 0; e < 4; ++e) acc[i][j][e] = 0.f;

    const unsigned lane_off = (unsigned)(lane & 15) * (2*WROW) + (unsigned)(lane >> 4) * 16u;

    for (int k = 0; k < K; ++k) {
        const unsigned buf = (unsigned)(k & 1);
        MBARRIER_WAIT_PARITY(mb + 8u*buf, (k >> 1) & 1);

        const unsigned Ab = smem + 2*BBUF + buf*ABUF;
        const unsigned Bb = smem + buf*BBUF;

#pragma unroll
        for (int ks = 0; ks < 8; ++ks) {
            unsigned a[4][4];
            unsigned abase = Ab + (unsigned)m0*(2*WROW) + (unsigned)ks*32u + lane_off;
#pragma unroll
            for (int q = 0; q < 4; ++q) ldsm_x4(a[q], abase + (unsigned)q*16u*(2*WROW));
            unsigned bbase = Bb + (unsigned)ks*16u*(2*WROW) + (unsigned)n0*2u + lane_off;
            unsigned b[4][4];
#pragma unroll
            for (int p = 0; p < 4; ++p) ldsm_x4_t(b[p], bbase + (unsigned)p*32u);
#pragma unroll
            for (int p = 0; p < 4; ++p) {
#pragma unroll
                for (int q = 0; q < 4; ++q) {
                    mma16816(acc[q][2*p],   a[q], b[p][0], b[p][1]);
                    mma16816(acc[q][2*p+1], a[q], b[p][2], b[p][3]);
                }
            }
        }

        FENCE_PROXY_ASYNC();
        __syncthreads();

        const int kn = k + 2;
        if (kn < K) {
            unsigned bar = mb + 8u*buf;
            MBARRIER_ARRIVE_EXPECT_TX(bar, 256u);
            int idx = nbrT[(size_t)kn * NPTS + row0 + tid];
            bulk_g2s(Ab + (unsigned)tid*(2*WROW), feats + (size_t)idx * CH, 256u, bar);
            if (tid == 0) {
                MBARRIER_ARRIVE_EXPECT_TX(bar, (unsigned)BBUF);
                bulk_g2s(Bb, Wb + (size_t)kn*(128*WROW), (unsigned)BBUF, bar);
            }
        }
    }

    // epilogue
#pragma unroll
    for (int msub = 0; msub < 4; ++msub) {
#pragma unroll
        for (int nb = 0; nb < 8; ++nb) {
#pragma unroll
            for (int ep = 0; ep < 2; ++ep) {
                int row = row0 + m0 + msub*16 + (lane >> 2) + ep*8;
                int col = n0 + nb*8 + (lane & 3)*2;
                float v0 = acc[msub][nb][ep*2];
                float v1 = acc[msub][nb][ep*2 + 1];
                size_t off = (size_t)row * CH + col;
                if (gate) {
                    float2 g = *reinterpret_cast<const float2*>(gate + off);
                    v0 *= g.x; v1 *= g.y;
                }
                if (out32) *reinterpret_cast<float2*>(out32 + off) = make_float2(v0, v1);
                if (out16) *reinterpret_cast<__half2*>(out16 + off) = __floats2half2_rn(v0, v1);
            }
        }
    }
}

// ======================= SIMT 1x1 GEMM (exact fp32, fused fp16 out) =========
#define TM 128
#define KC 32
#define SMEM_FLOATS (TM*CH + KC*CH + TM)
#define SMEM_BYTES  (SMEM_FLOATS * 4)
__global__ void __launch_bounds__(NT, 2)
sconv_kernel(const float* __restrict__ feats, const float* __restrict__ Wt,
             float* __restrict__ out32, __half* __restrict__ out16)
{
    extern __shared__ float smem[];
    float* Fs = smem;
    float* Ws = smem + TM*CH;
    const int tid = threadIdx.x;
    const int row0 = blockIdx.x * TM;
    const int tcx = tid & 15, tcy = tid >> 4;
    float acc[8][8];
#pragma unroll
    for (int r = 0; r < 8; ++r)
#pragma unroll
        for (int c = 0; c < 8; ++c) acc[r][c] = 0.f;

#pragma unroll
    for (int j = 0; j < (TM*CH/4)/NT; ++j) {
        int lin = tid + j*NT;
        int r = lin >> 5, c4 = lin & 31;
        reinterpret_cast<float4*>(Fs + r*CH)[c4] =
            reinterpret_cast<const float4*>(feats + (size_t)(row0 + r)*CH)[c4];
    }
#pragma unroll 1
    for (int cc = 0; cc < CH/KC; ++cc) {
        __syncthreads();
#pragma unroll
        for (int j = 0; j < 4; ++j) {
            int lin = tid + j*NT;
            reinterpret_cast<float4*>(Ws)[lin] =
                reinterpret_cast<const float4*>(Wt + cc*(KC*CH))[lin];
        }
        __syncthreads();
        const float* fp = Fs + (tcy*8)*CH + cc*KC;
        const float4* wrow = reinterpret_cast<const float4*>(Ws);
#pragma unroll 4
        for (int ci = 0; ci < KC; ++ci) {
            float f[8];
#pragma unroll
            for (int r = 0; r < 8; ++r) f[r] = fp[r*CH + ci];
            float4 w0 = wrow[ci*(CH/4) + tcx*2];
            float4 w1 = wrow[ci*(CH/4) + tcx*2 + 1];
            float wv[8] = {w0.x, w0.y, w0.z, w0.w, w1.x, w1.y, w1.z, w1.w};
#pragma unroll
            for (int r = 0; r < 8; ++r)
#pragma unroll
                for (int c = 0; c < 8; ++c)
                    acc[r][c] = fmaf(f[r], wv[c], acc[r][c]);
        }
    }
#pragma unroll
    for (int r = 0; r < 8; ++r) {
        size_t base = (size_t)(row0 + tcy*8 + r)*CH + tcx*8;
        if (out32) {
            *reinterpret_cast<float4*>(out32 + base)     = make_float4(acc[r][0],acc[r][1],acc[r][2],acc[r][3]);
            *reinterpret_cast<float4*>(out32 + base + 4) = make_float4(acc[r][4],acc[r][5],acc[r][6],acc[r][7]);
        }
        if (out16) {
            __half2* hp = reinterpret_cast<__half2*>(out16 + base);
            hp[0] = __floats2half2_rn(acc[r][0], acc[r][1]);
            hp[1] = __floats2half2_rn(acc[r][2], acc[r][3]);
            hp[2] = __floats2half2_rn(acc[r][4], acc[r][5]);
            hp[3] = __floats2half2_rn(acc[r][6], acc[r][7]);
        }
    }
}

// ======================= BN / elementwise =======================
__global__ void bn_partial_kernel(const float* __restrict__ y)
{
    int tid = threadIdx.x;
    int c = tid & (CH-1), half = tid >> 7;
    int rbase = blockIdx.x * 512 + half;
    float s = 0.f, s2 = 0.f;
#pragma unroll 8
    for (int j = 0; j < 256; ++j) {
        float v = y[(size_t)(rbase + 2*j)*CH + c];
        s += v; s2 = fmaf(v, v, s2);
    }
    g_part[blockIdx.x*256 + tid]          = s;
    g_part[64*256 + blockIdx.x*256 + tid] = s2;
}
__global__ void bn_finalize_kernel(const float* __restrict__ gamma, const float* __restrict__ beta)
{
    int c = threadIdx.x;
    float s = 0.f, s2 = 0.f;
    for (int b = 0; b < 64; ++b) {
        s  += g_part[b*256 + c] + g_part[b*256 + CH + c];
        s2 += g_part[64*256 + b*256 + c] + g_part[64*256 + b*256 + CH + c];
    }
    const float inv = 1.0f / (float)NPTS;
    float mu = s * inv;
    float var = s2 * inv - mu*mu;
    float sc = gamma[c] * rsqrtf(var + 1e-5f);
    g_scale[c] = sc;
    g_shift[c] = fmaf(-mu, sc, beta[c]);
}
// R = BN1(y)+x ; Th = fp16(relu(R))
__global__ void ew1_kernel(const float* __restrict__ y, const float* __restrict__ x)
{
    size_t i = (size_t)blockIdx.x * blockDim.x + threadIdx.x;
    float4 yv = reinterpret_cast<const float4*>(y)[i];
    float4 xv = reinterpret_cast<const float4*>(x)[i];
    int cg = (int)(i & 31);
    float4 sc = reinterpret_cast<const float4*>(g_scale)[cg];
    float4 sh = reinterpret_cast<const float4*>(g_shift)[cg];
    float4 r2;
    r2.x = fmaf(yv.x, sc.x, sh.x) + xv.x;
    r2.y = fmaf(yv.y, sc.y, sh.y) + xv.y;
    r2.z = fmaf(yv.z, sc.z, sh.z) + xv.z;
    r2.w = fmaf(yv.w, sc.w, sh.w) + xv.w;
    reinterpret_cast<float4*>(g_R)[i] = r2;
    reinterpret_cast<__half2*>(g_Th)[2*i]   = __floats2half2_rn(fmaxf(r2.x,0.f), fmaxf(r2.y,0.f));
    reinterpret_cast<__half2*>(g_Th)[2*i+1] = __floats2half2_rn(fmaxf(r2.z,0.f), fmaxf(r2.w,0.f));
}
// out = relu(BN2(y) + R)
__global__ void ew2_kernel(const float* __restrict__ y, float* __restrict__ out)
{
    size_t i = (size_t)blockIdx.x * blockDim.x + threadIdx.x;
    float4 yv = reinterpret_cast<const float4*>(y)[i];
    float4 rv = reinterpret_cast<const float4*>(g_R)[i];
    int cg = (int)(i & 31);
    float4 sc = reinterpret_cast<const float4*>(g_scale)[cg];
    float4 sh = reinterpret_cast<const float4*>(g_shift)[cg];
    float4 o;
    o.x = fmaxf(fmaf(yv.x, sc.x, sh.x) + rv.x, 0.f);
    o.y = fmaxf(fmaf(yv.y, sc.y, sh.y) + rv.y, 0.f);
    o.z = fmaxf(fmaf(yv.z, sc.z, sh.z) + rv.z, 0.f);
    o.w = fmaxf(fmaf(yv.w, sc.w, sh.w) + rv.w, 0.f);
    reinterpret_cast<float4*>(out)[i] = o;
}

// ======================= launch =======================
extern "C" void kernel_launch(void* const* d_in, const int* in_sizes, int n_in,
                              void* d_out, int out_size)
{
    const float* x      = (const float*)d_in[0];
    const float* Wa1    = (const float*)d_in[1];
    const float* Wv1    = (const float*)d_in[2];
    const float* W5     = (const float*)d_in[3];
    const float* W31    = (const float*)d_in[4];
    const float* W32    = (const float*)d_in[5];
    const float* gamma1 = (const float*)d_in[6];
    const float* beta1  = (const float*)d_in[7];
    const float* gamma2 = (const float*)d_in[8];
    const float* beta2  = (const float*)d_in[9];
    const int*   nbr5   = (const int*)d_in[10];
    const int*   nbr3a  = (const int*)d_in[11];
    const int*   nbr3b  = (const int*)d_in[12];
    float* out = (float*)d_out;

    float *pV, *pY;
    __half *pAh, *pGh, *pTh, *pW5b, *pW31b, *pW32b;
    int *pn5, *pn3a, *pn3b;
    cudaGetSymbolAddress((void**)&pV,  g_V);
    cudaGetSymbolAddress((void**)&pY,  g_Y);
    cudaGetSymbolAddress((void**)&pAh, g_Ah);
    cudaGetSymbolAddress((void**)&pGh, g_Gh);
    cudaGetSymbolAddress((void**)&pTh, g_Th);
    cudaGetSymbolAddress((void**)&pW5b, g_W5b);
    cudaGetSymbolAddress((void**)&pW31b, g_W31b);
    cudaGetSymbolAddress((void**)&pW32b, g_W32b);
    cudaGetSymbolAddress((void**)&pn5,  g_nT5);
    cudaGetSymbolAddress((void**)&pn3a, g_nT3a);
    cudaGetSymbolAddress((void**)&pn3b, g_nT3b);

    cudaFuncSetAttribute(sconv_kernel, cudaFuncAttributeMaxDynamicSharedMemorySize, SMEM_BYTES);
    cudaFuncSetAttribute(tconv_kernel, cudaFuncAttributeMaxDynamicSharedMemorySize, TCONV_SMEM);

    // --- prep: weight images, neighbor transposes ---
    wprep_kernel<<<125*64, 256>>>(W5,  pW5b);
    wprep_kernel<<<27*64, 256>>>(W31, pW31b);
    wprep_kernel<<<27*64, 256>>>(W32, pW32b);
    ntr_kernel<<<dim3(4, NPTS/32), 256>>>(nbr5,  pn5,  125);
    ntr_kernel<<<dim3(1, NPTS/32), 256>>>(nbr3a, pn3a, 27);
    ntr_kernel<<<dim3(1, NPTS/32), 256>>>(nbr3b, pn3b, 27);

    const int ggrid = NPTS / TM;          // 256
    const int tgrid = NPTS / MROWS;       // 128
    const int ewgrid = (NPTS*CH/4) / 256;

    // a = fp16(x @ Wa1) ; v = x @ Wv1 (fp32 gate)
    sconv_kernel<<<ggrid, NT, SMEM_BYTES>>>(x, Wa1, nullptr, pAh);
    sconv_kernel<<<ggrid, NT, SMEM_BYTES>>>(x, Wv1, pV, nullptr);
    // Gh = fp16( conv5(a) * v )
    tconv_kernel<<<tgrid, NT, TCONV_SMEM>>>(pAh, pW5b, pn5, 125, pV, pGh, nullptr);
    // Y = conv3a(G); BN1; R = bn+x; Th = fp16(relu(R))
    tconv_kernel<<<tgrid, NT, TCONV_SMEM>>>(pGh, pW31b, pn3a, 27, nullptr, nullptr, pY);
    bn_partial_kernel<<<64, 256>>>(pY);
    bn_finalize_kernel<<<1, 128>>>(gamma1, beta1);
    ew1_kernel<<<ewgrid, 256>>>(pY, x);
    // Y = conv3b(T); BN2; out = relu(bn + R)
    tconv_kernel<<<tgrid, NT, TCONV_SMEM>>>(pTh, pW32b, pn3b, 27, nullptr, nullptr, pY);
    bn_partial_kernel<<<64, 256>>>(pY);
    bn_finalize_kernel<<<1, 128>>>(gamma2, beta2);
    ew2_kernel<<<ewgrid, 256>>>(pY, out);
}

// round 6
// speedup vs baseline: 6.8904x; 1.0288x over previous
#include <cuda_runtime.h>
#include <cuda_fp16.h>

#define NPTS 32768
#define CH   128
#define NT   256

// ======================= baseline-PTX helpers =======================
__device__ __forceinline__ unsigned smem_to_u32(const void* p) {
    unsigned a;
    asm("{ .reg .u64 t; cvta.to.shared.u64 t, %1; cvt.u32.u64 %0, t; }" : "=r"(a) : "l"(p));
    return a;
}
__device__ __forceinline__ void cp16(unsigned dst, const void* src) {
    asm volatile("cp.async.cg.shared.global [%0], [%1], 16;" :: "r"(dst), "l"(src));
}
#define CP_COMMIT() asm volatile("cp.async.commit_group;" ::: "memory")
#define CP_WAIT(n)  asm volatile("cp.async.wait_group %0;" :: "n"(n) : "memory")

__device__ __forceinline__ void ldsm_x4(unsigned* r, unsigned addr) {
    asm volatile("ldmatrix.sync.aligned.m8n8.x4.shared.b16 {%0,%1,%2,%3}, [%4];"
        : "=r"(r[0]), "=r"(r[1]), "=r"(r[2]), "=r"(r[3]) : "r"(addr));
}
__device__ __forceinline__ void ldsm_x4_t(unsigned* r, unsigned addr) {
    asm volatile("ldmatrix.sync.aligned.m8n8.x4.trans.shared.b16 {%0,%1,%2,%3}, [%4];"
        : "=r"(r[0]), "=r"(r[1]), "=r"(r[2]), "=r"(r[3]) : "r"(addr));
}
__device__ __forceinline__ void mma16816(float* c, const unsigned* a, unsigned b0, unsigned b1) {
    asm volatile("mma.sync.aligned.m16n8k16.row.col.f32.f16.f16.f32 "
        "{%0,%1,%2,%3}, {%4,%5,%6,%7}, {%8,%9}, {%0,%1,%2,%3};"
        : "+f"(c[0]), "+f"(c[1]), "+f"(c[2]), "+f"(c[3])
        : "r"(a[0]), "r"(a[1]), "r"(a[2]), "r"(a[3]), "r"(b0), "r"(b1));
}

// ======================= sizes =======================
#define WROW   136
#define BBUF   (128*WROW*2)            // B bytes per tap = 34816
#define MROWS  256
#define ABUF   (MROWS*WROW*2)          // A tile bytes = 69632
#define TCONV_SMEM (2*BBUF + 2*ABUF)   // 208896

// ======================= scratch =======================
__device__ __align__(16) float  g_V [NPTS*CH];
__device__ __align__(16) float  g_Y [NPTS*CH];
__device__ __align__(16) float  g_R [NPTS*CH];
__device__ __align__(16) __half g_Xh[NPTS*CH];
__device__ __align__(16) __half g_Ah[NPTS*CH];
__device__ __align__(16) __half g_Gh[NPTS*CH];
__device__ __align__(16) __half g_Th[NPTS*CH];
__device__ __align__(16) __half g_W5b [125*128*WROW];
__device__ __align__(16) __half g_W31b[27*128*WROW];
__device__ __align__(16) __half g_W32b[27*128*WROW];
__device__ __align__(16) __half g_Wa1b[128*WROW];
__device__ __align__(16) __half g_Wv1b[128*WROW];
__device__ int g_nT5 [125*NPTS];
__device__ int g_nT3a[27*NPTS];
__device__ int g_nT3b[27*NPTS];
__device__ __align__(16) float g_part[2*64*256];
__device__ __align__(16) float g_scale[CH];
__device__ __align__(16) float g_shift[CH];

// ======================= prep kernels =======================
__global__ void wprep_kernel(const float* __restrict__ W, __half* __restrict__ Wb)
{
    int e = blockIdx.x * 256 + threadIdx.x;
    int k = e >> 14, r = e & 16383;
    int ci = r >> 7, co = r & 127;
    Wb[(size_t)k * (128*WROW) + ci*WROW + co] = __float2half_rn(W[e]);
}

__global__ void ntr_kernel(const int* __restrict__ nbr, int* __restrict__ nbrT, int K)
{
    __shared__ int t[32][33];
    int k0 = blockIdx.x * 32, i0 = blockIdx.y * 32;
    int tx = threadIdx.x & 31, ty = threadIdx.x >> 5;
#pragma unroll
    for (int r = 0; r < 32; r += 8) {
        int kk = k0 + tx;
        t[ty + r][tx] = (kk < K) ? nbr[(size_t)(i0 + ty + r) * K + kk] : 0;
    }
    __syncthreads();
#pragma unroll
    for (int r = 0; r < 32; r += 8) {
        int kk = k0 + ty + r;
        if (kk < K) nbrT[(size_t)kk * NPTS + i0 + tx] = t[tx][ty + r];
    }
}

__global__ void cvt_kernel(const float* __restrict__ in, __half* __restrict__ out)
{
    int i = blockIdx.x * 256 + threadIdx.x;       // float4 units
    float4 v = reinterpret_cast<const float4*>(in)[i];
    reinterpret_cast<__half2*>(out)[2*i]   = __floats2half2_rn(v.x, v.y);
    reinterpret_cast<__half2*>(out)[2*i+1] = __floats2half2_rn(v.z, v.w);
}

// ======================= HMMA gather-conv (cp.async pipeline) ===============
// out[i,:] = sum_k feats[nbr(k,i),:] @ W[k]; nbrT==null -> identity gather.
// CTA: 256 rows x 128 cols, 8 warps = 4(m) x 2(n), each warp M64 x N64.
__device__ __forceinline__ void issue_tap(
    unsigned smem, int buf, int t,
    const __half* feats, const __half* Wb, const int* nbrT,
    int row0, int tid)
{
    const unsigned Ab = smem + 2*BBUF + (unsigned)buf*ABUF;
    const unsigned Bb = smem + (unsigned)buf*BBUF;
    const int rbase = tid >> 4;
    const int chunk = tid & 15;
    // A gather: per j, each warp-instr covers 2 full rows (coalesced 256B)
#pragma unroll
    for (int j = 0; j < 16; ++j) {
        int row = rbase + 16*j;
        int idx = nbrT ? nbrT[(size_t)t*NPTS + row0 + row] : (row0 + row);
        cp16(Ab + (unsigned)row*(2*WROW) + (unsigned)chunk*16u,
             (const char*)(feats + (size_t)idx*CH) + chunk*16);
    }
    // B: linear 34816 bytes = 2176 x 16B
    const char* wsrc = (const char*)(Wb + (size_t)t*(128*WROW));
#pragma unroll
    for (int j = 0; j < 8; ++j) {
        int c = tid + j*256;
        cp16(Bb + (unsigned)c*16u, wsrc + (size_t)c*16);
    }
    if (tid < 128) {
        int c = tid + 2048;
        cp16(Bb + (unsigned)c*16u, wsrc + (size_t)c*16);
    }
}

__global__ void __launch_bounds__(NT, 1)
tconv_kernel(const __half* __restrict__ feats,
             const __half* __restrict__ Wb,     // [K][128][136] fp16
             const int*    __restrict__ nbrT,   // [K][NPTS] or null (identity)
             const int K,
             const float*  __restrict__ gate,   // fp32 or null
             __half* __restrict__ out16,        // or null
             float*  __restrict__ out32)        // or null
{
    extern __shared__ char dsm[];
    const int tid  = threadIdx.x;
    const int lane = tid & 31;
    const int w    = tid >> 5;
    const int row0 = blockIdx.x * MROWS;
    const int m0   = (w >> 1) * 64;
    const int n0   = (w & 1) * 64;
    const unsigned smem = smem_to_u32(dsm);

    // prologue: taps 0,1
    issue_tap(smem, 0, 0, feats, Wb, nbrT, row0, tid);
    CP_COMMIT();
    if (1 < K) {
        issue_tap(smem, 1, 1, feats, Wb, nbrT, row0, tid);
        CP_COMMIT();
    }

    float acc[4][8][4];
#pragma unroll
    for (int i = 0; i < 4; ++i)
#pragma unroll
        for (int j = 0; j < 8; ++j)
#pragma unroll
            for (int e = 0; e < 4; ++e) acc[i][j][e] = 0.f;

    const unsigned lane_off = (unsigned)(lane & 15) * (2*WROW) + (unsigned)(lane >> 4) * 16u;

    for (int k = 0; k < K; ++k) {
        const int buf = k & 1;
        if (k + 1 < K) { CP_WAIT(1); } else { CP_WAIT(0); }
        __syncthreads();

        const unsigned Ab = smem + 2*BBUF + (unsigned)buf*ABUF;
        const unsigned Bb = smem + (unsigned)buf*BBUF;

#pragma unroll
        for (int ks = 0; ks < 8; ++ks) {
            unsigned a[4][4];
            unsigned abase = Ab + (unsigned)m0*(2*WROW) + (unsigned)ks*32u + lane_off;
#pragma unroll
            for (int q = 0; q < 4; ++q) ldsm_x4(a[q], abase + (unsigned)q*16u*(2*WROW));
            unsigned bbase = Bb + (unsigned)ks*16u*(2*WROW) + (unsigned)n0*2u + lane_off;
            unsigned b[4][4];
#pragma unroll
            for (int p = 0; p < 4; ++p) ldsm_x4_t(b[p], bbase + (unsigned)p*32u);
#pragma unroll
            for (int p = 0; p < 4; ++p) {
#pragma unroll
                for (int q = 0; q < 4; ++q) {
                    mma16816(acc[q][2*p],   a[q], b[p][0], b[p][1]);
                    mma16816(acc[q][2*p+1], a[q], b[p][2], b[p][3]);
                }
            }
        }

        __syncthreads();   // everyone done reading buf before refilling it

        const int kn = k + 2;
        if (kn < K) {
            issue_tap(smem, buf, kn, feats, Wb, nbrT, row0, tid);
            CP_COMMIT();
        }
    }

    // epilogue
#pragma unroll
    for (int msub = 0; msub < 4; ++msub) {
#pragma unroll
        for (int nb = 0; nb < 8; ++nb) {
#pragma unroll
            for (int ep = 0; ep < 2; ++ep) {
                int row = row0 + m0 + msub*16 + (lane >> 2) + ep*8;
                int col = n0 + nb*8 + (lane & 3)*2;
                float v0 = acc[msub][nb][ep*2];
                float v1 = acc[msub][nb][ep*2 + 1];
                size_t off = (size_t)row * CH + col;
                if (gate) {
                    float2 g = *reinterpret_cast<const float2*>(gate + off);
                    v0 *= g.x; v1 *= g.y;
                }
                if (out32) *reinterpret_cast<float2*>(out32 + off) = make_float2(v0, v1);
                if (out16) *reinterpret_cast<__half2*>(out16 + off) = __floats2half2_rn(v0, v1);
            }
        }
    }
}

// ======================= BN / elementwise =======================
__global__ void bn_partial_kernel(const float* __restrict__ y)
{
    int tid = threadIdx.x;
    int c = tid & (CH-1), half = tid >> 7;
    int rbase = blockIdx.x * 512 + half;
    float s = 0.f, s2 = 0.f;
#pragma unroll 8
    for (int j = 0; j < 256; ++j) {
        float v = y[(size_t)(rbase + 2*j)*CH + c];
        s += v; s2 = fmaf(v, v, s2);
    }
    g_part[blockIdx.x*256 + tid]          = s;
    g_part[64*256 + blockIdx.x*256 + tid] = s2;
}
__global__ void bn_finalize_kernel(const float* __restrict__ gamma, const float* __restrict__ beta)
{
    int c = threadIdx.x;
    float s = 0.f, s2 = 0.f;
    for (int b = 0; b < 64; ++b) {
        s  += g_part[b*256 + c] + g_part[b*256 + CH + c];
        s2 += g_part[64*256 + b*256 + c] + g_part[64*256 + b*256 + CH + c];
    }
    const float inv = 1.0f / (float)NPTS;
    float mu = s * inv;
    float var = s2 * inv - mu*mu;
    float sc = gamma[c] * rsqrtf(var + 1e-5f);
    g_scale[c] = sc;
    g_shift[c] = fmaf(-mu, sc, beta[c]);
}
// R = BN1(y)+x ; Th = fp16(relu(R))
__global__ void ew1_kernel(const float* __restrict__ y, const float* __restrict__ x)
{
    size_t i = (size_t)blockIdx.x * blockDim.x + threadIdx.x;
    float4 yv = reinterpret_cast<const float4*>(y)[i];
    float4 xv = reinterpret_cast<const float4*>(x)[i];
    int cg = (int)(i & 31);
    float4 sc = reinterpret_cast<const float4*>(g_scale)[cg];
    float4 sh = reinterpret_cast<const float4*>(g_shift)[cg];
    float4 r2;
    r2.x = fmaf(yv.x, sc.x, sh.x) + xv.x;
    r2.y = fmaf(yv.y, sc.y, sh.y) + xv.y;
    r2.z = fmaf(yv.z, sc.z, sh.z) + xv.z;
    r2.w = fmaf(yv.w, sc.w, sh.w) + xv.w;
    reinterpret_cast<float4*>(g_R)[i] = r2;
    reinterpret_cast<__half2*>(g_Th)[2*i]   = __floats2half2_rn(fmaxf(r2.x,0.f), fmaxf(r2.y,0.f));
    reinterpret_cast<__half2*>(g_Th)[2*i+1] = __floats2half2_rn(fmaxf(r2.z,0.f), fmaxf(r2.w,0.f));
}
// out = relu(BN2(y) + R)
__global__ void ew2_kernel(const float* __restrict__ y, float* __restrict__ out)
{
    size_t i = (size_t)blockIdx.x * blockDim.x + threadIdx.x;
    float4 yv = reinterpret_cast<const float4*>(y)[i];
    float4 rv = reinterpret_cast<const float4*>(g_R)[i];
    int cg = (int)(i & 31);
    float4 sc = reinterpret_cast<const float4*>(g_scale)[cg];
    float4 sh = reinterpret_cast<const float4*>(g_shift)[cg];
    float4 o;
    o.x = fmaxf(fmaf(yv.x, sc.x, sh.x) + rv.x, 0.f);
    o.y = fmaxf(fmaf(yv.y, sc.y, sh.y) + rv.y, 0.f);
    o.z = fmaxf(fmaf(yv.z, sc.z, sh.z) + rv.z, 0.f);
    o.w = fmaxf(fmaf(yv.w, sc.w, sh.w) + rv.w, 0.f);
    reinterpret_cast<float4*>(out)[i] = o;
}

// ======================= launch =======================
extern "C" void kernel_launch(void* const* d_in, const int* in_sizes, int n_in,
                              void* d_out, int out_size)
{
    const float* x      = (const float*)d_in[0];
    const float* Wa1    = (const float*)d_in[1];
    const float* Wv1    = (const float*)d_in[2];
    const float* W5     = (const float*)d_in[3];
    const float* W31    = (const float*)d_in[4];
    const float* W32    = (const float*)d_in[5];
    const float* gamma1 = (const float*)d_in[6];
    const float* beta1  = (const float*)d_in[7];
    const float* gamma2 = (const float*)d_in[8];
    const float* beta2  = (const float*)d_in[9];
    const int*   nbr5   = (const int*)d_in[10];
    const int*   nbr3a  = (const int*)d_in[11];
    const int*   nbr3b  = (const int*)d_in[12];
    float* out = (float*)d_out;

    float *pV, *pY;
    __half *pXh, *pAh, *pGh, *pTh, *pW5b, *pW31b, *pW32b, *pWa1b, *pWv1b;
    int *pn5, *pn3a, *pn3b;
    cudaGetSymbolAddress((void**)&pV,  g_V);
    cudaGetSymbolAddress((void**)&pY,  g_Y);
    cudaGetSymbolAddress((void**)&pXh, g_Xh);
    cudaGetSymbolAddress((void**)&pAh, g_Ah);
    cudaGetSymbolAddress((void**)&pGh, g_Gh);
    cudaGetSymbolAddress((void**)&pTh, g_Th);
    cudaGetSymbolAddress((void**)&pW5b, g_W5b);
    cudaGetSymbolAddress((void**)&pW31b, g_W31b);
    cudaGetSymbolAddress((void**)&pW32b, g_W32b);
    cudaGetSymbolAddress((void**)&pWa1b, g_Wa1b);
    cudaGetSymbolAddress((void**)&pWv1b, g_Wv1b);
    cudaGetSymbolAddress((void**)&pn5,  g_nT5);
    cudaGetSymbolAddress((void**)&pn3a, g_nT3a);
    cudaGetSymbolAddress((void**)&pn3b, g_nT3b);

    cudaFuncSetAttribute(tconv_kernel, cudaFuncAttributeMaxDynamicSharedMemorySize, TCONV_SMEM);

    // --- prep ---
    wprep_kernel<<<125*64, 256>>>(W5,  pW5b);
    wprep_kernel<<<27*64, 256>>>(W31, pW31b);
    wprep_kernel<<<27*64, 256>>>(W32, pW32b);
    wprep_kernel<<<64, 256>>>(Wa1, pWa1b);
    wprep_kernel<<<64, 256>>>(Wv1, pWv1b);
    ntr_kernel<<<dim3(4, NPTS/32), 256>>>(nbr5,  pn5,  125);
    ntr_kernel<<<dim3(1, NPTS/32), 256>>>(nbr3a, pn3a, 27);
    ntr_kernel<<<dim3(1, NPTS/32), 256>>>(nbr3b, pn3b, 27);

    const int tgrid = NPTS / MROWS;       // 128
    const int ewgrid = (NPTS*CH/4) / 256;

    // xh = fp16(x); a = fp16(xh @ Wa1); v = fp32(xh @ Wv1)
    cvt_kernel<<<ewgrid, 256>>>(x, pXh);
    tconv_kernel<<<tgrid, NT, TCONV_SMEM>>>(pXh, pWa1b, nullptr, 1, nullptr, pAh, nullptr);
    tconv_kernel<<<tgrid, NT, TCONV_SMEM>>>(pXh, pWv1b, nullptr, 1, nullptr, nullptr, pV);
    // Gh = fp16( conv5(a) * v )
    tconv_kernel<<<tgrid, NT, TCONV_SMEM>>>(pAh, pW5b, pn5, 125, pV, pGh, nullptr);
    // Y = conv3a(G); BN1; R = bn+x; Th = fp16(relu(R))
    tconv_kernel<<<tgrid, NT, TCONV_SMEM>>>(pGh, pW31b, pn3a, 27, nullptr, nullptr, pY);
    bn_partial_kernel<<<64, 256>>>(pY);
    bn_finalize_kernel<<<1, 128>>>(gamma1, beta1);
    ew1_kernel<<<ewgrid, 256>>>(pY, x);
    // Y = conv3b(T); BN2; out = relu(bn + R)
    tconv_kernel<<<tgrid, NT, TCONV_SMEM>>>(pTh, pW32b, pn3b, 27, nullptr, nullptr, pY);
    bn_partial_kernel<<<64, 256>>>(pY);
    bn_finalize_kernel<<<1, 128>>>(gamma2, beta2);
    ew2_kernel<<<ewgrid, 256>>>(pY, out);
}

// round 7
// speedup vs baseline: 7.0837x; 1.0281x over previous
#include <cuda_runtime.h>
#include <cuda_fp16.h>

#define NPTS 32768
#define CH   128
#define NT   256

// ======================= baseline-PTX helpers =======================
__device__ __forceinline__ unsigned smem_to_u32(const void* p) {
    unsigned a;
    asm("{ .reg .u64 t; cvta.to.shared.u64 t, %1; cvt.u32.u64 %0, t; }" : "=r"(a) : "l"(p));
    return a;
}
__device__ __forceinline__ void cp16(unsigned dst, const void* src) {
    asm volatile("cp.async.cg.shared.global [%0], [%1], 16;" :: "r"(dst), "l"(src));
}
#define CP_COMMIT() asm volatile("cp.async.commit_group;" ::: "memory")
#define CP_WAIT(n)  asm volatile("cp.async.wait_group %0;" :: "n"(n) : "memory")

__device__ __forceinline__ void ldsm_x4(unsigned* r, unsigned addr) {
    asm volatile("ldmatrix.sync.aligned.m8n8.x4.shared.b16 {%0,%1,%2,%3}, [%4];"
        : "=r"(r[0]), "=r"(r[1]), "=r"(r[2]), "=r"(r[3]) : "r"(addr));
}
__device__ __forceinline__ void ldsm_x4_t(unsigned* r, unsigned addr) {
    asm volatile("ldmatrix.sync.aligned.m8n8.x4.trans.shared.b16 {%0,%1,%2,%3}, [%4];"
        : "=r"(r[0]), "=r"(r[1]), "=r"(r[2]), "=r"(r[3]) : "r"(addr));
}
__device__ __forceinline__ void mma16816(float* c, const unsigned* a, unsigned b0, unsigned b1) {
    asm volatile("mma.sync.aligned.m16n8k16.row.col.f32.f16.f16.f32 "
        "{%0,%1,%2,%3}, {%4,%5,%6,%7}, {%8,%9}, {%0,%1,%2,%3};"
        : "+f"(c[0]), "+f"(c[1]), "+f"(c[2]), "+f"(c[3])
        : "r"(a[0]), "r"(a[1]), "r"(a[2]), "r"(a[3]), "r"(b0), "r"(b1));
}

// ======================= sizes =======================
#define WROW   136
#define BBUF   (128*WROW*2)            // B bytes per tap = 34816
#define MROWS  256
#define ABUF   (MROWS*WROW*2)          // A tile bytes = 69632
#define TCONV_SMEM (2*BBUF + 2*ABUF)   // 208896

// ======================= scratch =======================
__device__ __align__(16) float  g_V [NPTS*CH];
__device__ __align__(16) float  g_Y [NPTS*CH];   // conv5 raw out, then conv3 outs
__device__ __align__(16) float  g_R [NPTS*CH];
__device__ __align__(16) __half g_Ah[NPTS*CH];
__device__ __align__(16) __half g_Gh[NPTS*CH];
__device__ __align__(16) __half g_Th[NPTS*CH];
__device__ __align__(16) __half g_W5b [125*128*WROW];
__device__ __align__(16) __half g_W31b[27*128*WROW];
__device__ __align__(16) __half g_W32b[27*128*WROW];
__device__ int g_nT5 [125*NPTS];
__device__ int g_nT3a[27*NPTS];
__device__ int g_nT3b[27*NPTS];
__device__ __align__(16) float g_part[2*64*256];
__device__ __align__(16) float g_scale[CH];
__device__ __align__(16) float g_shift[CH];

// ======================= prep kernels (fused) =======================
// All three conv weight tensors -> fp16 padded images in ONE launch.
__global__ void wprep_all(const float* __restrict__ W5, const float* __restrict__ W31,
                          const float* __restrict__ W32,
                          __half* __restrict__ o5, __half* __restrict__ o31,
                          __half* __restrict__ o32)
{
    int b = blockIdx.x;                 // 179*64 blocks
    const float* W; __half* O; int kb;
    if (b < 125*64)      { W = W5;  O = o5;  kb = b; }
    else if (b < 152*64) { W = W31; O = o31; kb = b - 125*64; }
    else                 { W = W32; O = o32; kb = b - 152*64; }
    int e = kb * 256 + threadIdx.x;
    int k = e >> 14, r = e & 16383;
    int ci = r >> 7, co = r & 127;
    O[(size_t)k * (128*WROW) + ci*WROW + co] = __float2half_rn(W[e]);
}

// All three neighbor transposes in ONE launch. bx: 0-3 nbr5 ktile, 4 nbr3a, 5 nbr3b.
__global__ void ntr_all(const int* __restrict__ nbr5, const int* __restrict__ nbr3a,
                        const int* __restrict__ nbr3b,
                        int* __restrict__ n5, int* __restrict__ n3a, int* __restrict__ n3b)
{
    __shared__ int t[32][33];
    int bx = blockIdx.x;
    const int* src; int* dst; int K, k0;
    if (bx < 4)       { src = nbr5;  dst = n5;  K = 125; k0 = bx*32; }
    else if (bx == 4) { src = nbr3a; dst = n3a; K = 27;  k0 = 0; }
    else              { src = nbr3b; dst = n3b; K = 27;  k0 = 0; }
    int i0 = blockIdx.y * 32;
    int tx = threadIdx.x & 31, ty = threadIdx.x >> 5;
#pragma unroll
    for (int r = 0; r < 32; r += 8) {
        int kk = k0 + tx;
        t[ty + r][tx] = (kk < K) ? src[(size_t)(i0 + ty + r) * K + kk] : 0;
    }
    __syncthreads();
#pragma unroll
    for (int r = 0; r < 32; r += 8) {
        int kk = k0 + ty + r;
        if (kk < K) dst[(size_t)kk * NPTS + i0 + tx] = t[tx][ty + r];
    }
}

// ======================= HMMA gather-conv (cp.async pipeline) ===============
__device__ __forceinline__ void issue_tap(
    unsigned smem, int buf, int t,
    const __half* feats, const __half* Wb, const int* nbrT,
    int row0, int tid)
{
    const unsigned Ab = smem + 2*BBUF + (unsigned)buf*ABUF;
    const unsigned Bb = smem + (unsigned)buf*BBUF;
    // B first (contiguous): 34816 B = 2176 x 16B
    const char* wsrc = (const char*)(Wb + (size_t)t*(128*WROW));
#pragma unroll
    for (int j = 0; j < 8; ++j) {
        int c = tid + j*256;
        cp16(Bb + (unsigned)c*16u, wsrc + (size_t)c*16);
    }
    if (tid < 128) {
        int c = tid + 2048;
        cp16(Bb + (unsigned)c*16u, wsrc + (size_t)c*16);
    }
    // A gather: each warp-instr covers 2 full rows (coalesced 256B)
    const int rbase = tid >> 4;
    const int chunk = tid & 15;
#pragma unroll
    for (int j = 0; j < 16; ++j) {
        int row = rbase + 16*j;
        int idx = nbrT ? nbrT[(size_t)t*NPTS + row0 + row] : (row0 + row);
        cp16(Ab + (unsigned)row*(2*WROW) + (unsigned)chunk*16u,
             (const char*)(feats + (size_t)idx*CH) + chunk*16);
    }
}

__global__ void __launch_bounds__(NT, 1)
tconv_kernel(const __half* __restrict__ feats,
             const __half* __restrict__ Wb,     // [K][128][136] fp16
             const int*    __restrict__ nbrT,   // [K][NPTS] or null (identity)
             const int K,
             const float*  __restrict__ gate,   // fp32 or null
             __half* __restrict__ out16,        // or null
             float*  __restrict__ out32)        // or null
{
    extern __shared__ char dsm[];
    const int tid  = threadIdx.x;
    const int lane = tid & 31;
    const int w    = tid >> 5;
    const int row0 = blockIdx.x * MROWS;
    const int m0   = (w >> 1) * 64;
    const int n0   = (w & 1) * 64;
    const unsigned smem = smem_to_u32(dsm);

    // prologue: taps 0,1
    issue_tap(smem, 0, 0, feats, Wb, nbrT, row0, tid);
    CP_COMMIT();
    if (1 < K) {
        issue_tap(smem, 1, 1, feats, Wb, nbrT, row0, tid);
        CP_COMMIT();
    }

    float acc[4][8][4];
#pragma unroll
    for (int i = 0; i < 4; ++i)
#pragma unroll
        for (int j = 0; j < 8; ++j)
#pragma unroll
            for (int e = 0; e < 4; ++e) acc[i][j][e] = 0.f;

    const unsigned lane_off = (unsigned)(lane & 15) * (2*WROW) + (unsigned)(lane >> 4) * 16u;

    for (int k = 0; k < K; ++k) {
        const int buf = k & 1;
        if (k + 1 < K) { CP_WAIT(1); } else { CP_WAIT(0); }
        __syncthreads();

        const unsigned Ab = smem + 2*BBUF + (unsigned)buf*ABUF;
        const unsigned Bb = smem + (unsigned)buf*BBUF;

#pragma unroll
        for (int ks = 0; ks < 8; ++ks) {
            unsigned a[4][4];
            unsigned abase = Ab + (unsigned)m0*(2*WROW) + (unsigned)ks*32u + lane_off;
#pragma unroll
            for (int q = 0; q < 4; ++q) ldsm_x4(a[q], abase + (unsigned)q*16u*(2*WROW));
            unsigned bbase = Bb + (unsigned)ks*16u*(2*WROW) + (unsigned)n0*2u + lane_off;
            unsigned b[4][4];
#pragma unroll
            for (int p = 0; p < 4; ++p) ldsm_x4_t(b[p], bbase + (unsigned)p*32u);
#pragma unroll
            for (int p = 0; p < 4; ++p) {
#pragma unroll
                for (int q = 0; q < 4; ++q) {
                    mma16816(acc[q][2*p],   a[q], b[p][0], b[p][1]);
                    mma16816(acc[q][2*p+1], a[q], b[p][2], b[p][3]);
                }
            }
        }

        __syncthreads();   // all warps done reading buf before refill

        const int kn = k + 2;
        if (kn < K) {
            issue_tap(smem, buf, kn, feats, Wb, nbrT, row0, tid);
            CP_COMMIT();
        }
    }

    // epilogue
#pragma unroll
    for (int msub = 0; msub < 4; ++msub) {
#pragma unroll
        for (int nb = 0; nb < 8; ++nb) {
#pragma unroll
            for (int ep = 0; ep < 2; ++ep) {
                int row = row0 + m0 + msub*16 + (lane >> 2) + ep*8;
                int col = n0 + nb*8 + (lane & 3)*2;
                float v0 = acc[msub][nb][ep*2];
                float v1 = acc[msub][nb][ep*2 + 1];
                size_t off = (size_t)row * CH + col;
                if (gate) {
                    float2 g = *reinterpret_cast<const float2*>(gate + off);
                    v0 *= g.x; v1 *= g.y;
                }
                if (out32) *reinterpret_cast<float2*>(out32 + off) = make_float2(v0, v1);
                if (out16) *reinterpret_cast<__half2*>(out16 + off) = __floats2half2_rn(v0, v1);
            }
        }
    }
}

// ======================= SIMT 1x1 GEMM (exact fp32, fused fp16 out) =========
#define TM 128
#define KC 32
#define SMEM_FLOATS (TM*CH + KC*CH + TM)
#define SMEM_BYTES  (SMEM_FLOATS * 4)
__global__ void __launch_bounds__(NT, 2)
sconv_kernel(const float* __restrict__ feats, const float* __restrict__ Wt,
             float* __restrict__ out32, __half* __restrict__ out16)
{
    extern __shared__ float smem[];
    float* Fs = smem;
    float* Ws = smem + TM*CH;
    const int tid = threadIdx.x;
    const int row0 = blockIdx.x * TM;
    const int tcx = tid & 15, tcy = tid >> 4;
    float acc[8][8];
#pragma unroll
    for (int r = 0; r < 8; ++r)
#pragma unroll
        for (int c = 0; c < 8; ++c) acc[r][c] = 0.f;

#pragma unroll
    for (int j = 0; j < (TM*CH/4)/NT; ++j) {
        int lin = tid + j*NT;
        int r = lin >> 5, c4 = lin & 31;
        reinterpret_cast<float4*>(Fs + r*CH)[c4] =
            reinterpret_cast<const float4*>(feats + (size_t)(row0 + r)*CH)[c4];
    }
#pragma unroll 1
    for (int cc = 0; cc < CH/KC; ++cc) {
        __syncthreads();
#pragma unroll
        for (int j = 0; j < 4; ++j) {
            int lin = tid + j*NT;
            reinterpret_cast<float4*>(Ws)[lin] =
                reinterpret_cast<const float4*>(Wt + cc*(KC*CH))[lin];
        }
        __syncthreads();
        const float* fp = Fs + (tcy*8)*CH + cc*KC;
        const float4* wrow = reinterpret_cast<const float4*>(Ws);
#pragma unroll 4
        for (int ci = 0; ci < KC; ++ci) {
            float f[8];
#pragma unroll
            for (int r = 0; r < 8; ++r) f[r] = fp[r*CH + ci];
            float4 w0 = wrow[ci*(CH/4) + tcx*2];
            float4 w1 = wrow[ci*(CH/4) + tcx*2 + 1];
            float wv[8] = {w0.x, w0.y, w0.z, w0.w, w1.x, w1.y, w1.z, w1.w};
#pragma unroll
            for (int r = 0; r < 8; ++r)
#pragma unroll
                for (int c = 0; c < 8; ++c)
                    acc[r][c] = fmaf(f[r], wv[c], acc[r][c]);
        }
    }
#pragma unroll
    for (int r = 0; r < 8; ++r) {
        size_t base = (size_t)(row0 + tcy*8 + r)*CH + tcx*8;
        if (out32) {
            *reinterpret_cast<float4*>(out32 + base)     = make_float4(acc[r][0],acc[r][1],acc[r][2],acc[r][3]);
            *reinterpret_cast<float4*>(out32 + base + 4) = make_float4(acc[r][4],acc[r][5],acc[r][6],acc[r][7]);
        }
        if (out16) {
            __half2* hp = reinterpret_cast<__half2*>(out16 + base);
            hp[0] = __floats2half2_rn(acc[r][0], acc[r][1]);
            hp[1] = __floats2half2_rn(acc[r][2], acc[r][3]);
            hp[2] = __floats2half2_rn(acc[r][4], acc[r][5]);
            hp[3] = __floats2half2_rn(acc[r][6], acc[r][7]);
        }
    }
}

// ======================= BN / elementwise =======================
// Gh = fp16(y5 * v)
__global__ void gate_kernel(const float* __restrict__ y5, const float* __restrict__ v,
                            __half* __restrict__ gh)
{
    size_t i = (size_t)blockIdx.x * blockDim.x + threadIdx.x;  // float4 units
    float4 a = reinterpret_cast<const float4*>(y5)[i];
    float4 g = reinterpret_cast<const float4*>(v)[i];
    reinterpret_cast<__half2*>(gh)[2*i]   = __floats2half2_rn(a.x*g.x, a.y*g.y);
    reinterpret_cast<__half2*>(gh)[2*i+1] = __floats2half2_rn(a.z*g.z, a.w*g.w);
}

__global__ void bn_partial_kernel(const float* __restrict__ y)
{
    int tid = threadIdx.x;
    int c = tid & (CH-1), half = tid >> 7;
    int rbase = blockIdx.x * 512 + half;
    float s = 0.f, s2 = 0.f;
#pragma unroll 8
    for (int j = 0; j < 256; ++j) {
        float v = y[(size_t)(rbase + 2*j)*CH + c];
        s += v; s2 = fmaf(v, v, s2);
    }
    g_part[blockIdx.x*256 + tid]          = s;
    g_part[64*256 + blockIdx.x*256 + tid] = s2;
}
__global__ void bn_finalize_kernel(const float* __restrict__ gamma, const float* __restrict__ beta)
{
    int c = threadIdx.x;
    float s = 0.f, s2 = 0.f;
    for (int b = 0; b < 64; ++b) {
        s  += g_part[b*256 + c] + g_part[b*256 + CH + c];
        s2 += g_part[64*256 + b*256 + c] + g_part[64*256 + b*256 + CH + c];
    }
    const float inv = 1.0f / (float)NPTS;
    float mu = s * inv;
    float var = s2 * inv - mu*mu;
    float sc = gamma[c] * rsqrtf(var + 1e-5f);
    g_scale[c] = sc;
    g_shift[c] = fmaf(-mu, sc, beta[c]);
}
// R = BN1(y)+x ; Th = fp16(relu(R))
__global__ void ew1_kernel(const float* __restrict__ y, const float* __restrict__ x)
{
    size_t i = (size_t)blockIdx.x * blockDim.x + threadIdx.x;
    float4 yv = reinterpret_cast<const float4*>(y)[i];
    float4 xv = reinterpret_cast<const float4*>(x)[i];
    int cg = (int)(i & 31);
    float4 sc = reinterpret_cast<const float4*>(g_scale)[cg];
    float4 sh = reinterpret_cast<const float4*>(g_shift)[cg];
    float4 r2;
    r2.x = fmaf(yv.x, sc.x, sh.x) + xv.x;
    r2.y = fmaf(yv.y, sc.y, sh.y) + xv.y;
    r2.z = fmaf(yv.z, sc.z, sh.z) + xv.z;
    r2.w = fmaf(yv.w, sc.w, sh.w) + xv.w;
    reinterpret_cast<float4*>(g_R)[i] = r2;
    reinterpret_cast<__half2*>(g_Th)[2*i]   = __floats2half2_rn(fmaxf(r2.x,0.f), fmaxf(r2.y,0.f));
    reinterpret_cast<__half2*>(g_Th)[2*i+1] = __floats2half2_rn(fmaxf(r2.z,0.f), fmaxf(r2.w,0.f));
}
// out = relu(BN2(y) + R)
__global__ void ew2_kernel(const float* __restrict__ y, float* __restrict__ out)
{
    size_t i = (size_t)blockIdx.x * blockDim.x + threadIdx.x;
    float4 yv = reinterpret_cast<const float4*>(y)[i];
    float4 rv = reinterpret_cast<const float4*>(g_R)[i];
    int cg = (int)(i & 31);
    float4 sc = reinterpret_cast<const float4*>(g_scale)[cg];
    float4 sh = reinterpret_cast<const float4*>(g_shift)[cg];
    float4 o;
    o.x = fmaxf(fmaf(yv.x, sc.x, sh.x) + rv.x, 0.f);
    o.y = fmaxf(fmaf(yv.y, sc.y, sh.y) + rv.y, 0.f);
    o.z = fmaxf(fmaf(yv.z, sc.z, sh.z) + rv.z, 0.f);
    o.w = fmaxf(fmaf(yv.w, sc.w, sh.w) + rv.w, 0.f);
    reinterpret_cast<float4*>(out)[i] = o;
}

// ======================= launch =======================
extern "C" void kernel_launch(void* const* d_in, const int* in_sizes, int n_in,
                              void* d_out, int out_size)
{
    const float* x      = (const float*)d_in[0];
    const float* Wa1    = (const float*)d_in[1];
    const float* Wv1    = (const float*)d_in[2];
    const float* W5     = (const float*)d_in[3];
    const float* W31    = (const float*)d_in[4];
    const float* W32    = (const float*)d_in[5];
    const float* gamma1 = (const float*)d_in[6];
    const float* beta1  = (const float*)d_in[7];
    const float* gamma2 = (const float*)d_in[8];
    const float* beta2  = (const float*)d_in[9];
    const int*   nbr5   = (const int*)d_in[10];
    const int*   nbr3a  = (const int*)d_in[11];
    const int*   nbr3b  = (const int*)d_in[12];
    float* out = (float*)d_out;

    float *pV, *pY;
    __half *pAh, *pGh, *pTh, *pW5b, *pW31b, *pW32b;
    int *pn5, *pn3a, *pn3b;
    cudaGetSymbolAddress((void**)&pV,  g_V);
    cudaGetSymbolAddress((void**)&pY,  g_Y);
    cudaGetSymbolAddress((void**)&pAh, g_Ah);
    cudaGetSymbolAddress((void**)&pGh, g_Gh);
    cudaGetSymbolAddress((void**)&pTh, g_Th);
    cudaGetSymbolAddress((void**)&pW5b, g_W5b);
    cudaGetSymbolAddress((void**)&pW31b, g_W31b);
    cudaGetSymbolAddress((void**)&pW32b, g_W32b);
    cudaGetSymbolAddress((void**)&pn5,  g_nT5);
    cudaGetSymbolAddress((void**)&pn3a, g_nT3a);
    cudaGetSymbolAddress((void**)&pn3b, g_nT3b);

    cudaFuncSetAttribute(sconv_kernel, cudaFuncAttributeMaxDynamicSharedMemorySize, SMEM_BYTES);
    cudaFuncSetAttribute(tconv_kernel, cudaFuncAttributeMaxDynamicSharedMemorySize, TCONV_SMEM);

    const int ggrid = NPTS / TM;          // 256
    const int tgrid = NPTS / MROWS;       // 128
    const int ewgrid = (NPTS*CH/4) / 256;

    // 1: all weight images                  2: all neighbor transposes
    wprep_all<<<179*64, 256>>>(W5, W31, W32, pW5b, pW31b, pW32b);
    ntr_all<<<dim3(6, NPTS/32), 256>>>(nbr5, nbr3a, nbr3b, pn5, pn3a, pn3b);
    // 3: a = fp16(x @ Wa1)
    sconv_kernel<<<ggrid, NT, SMEM_BYTES>>>(x, Wa1, nullptr, pAh);
    // 4: conv5 raw (fp32) -- ncu captures this launch
    tconv_kernel<<<tgrid, NT, TCONV_SMEM>>>(pAh, pW5b, pn5, 125, nullptr, nullptr, pY);
    // 5: v = fp32(x @ Wv1)
    sconv_kernel<<<ggrid, NT, SMEM_BYTES>>>(x, Wv1, pV, nullptr);
    // 6: Gh = fp16(conv5 * v)
    gate_kernel<<<ewgrid, 256>>>(pY, pV, pGh);
    // 7: conv3a -> Y; BN1; R = bn+x; Th = fp16(relu(R))
    tconv_kernel<<<tgrid, NT, TCONV_SMEM>>>(pGh, pW31b, pn3a, 27, nullptr, nullptr, pY);
    bn_partial_kernel<<<64, 256>>>(pY);
    bn_finalize_kernel<<<1, 128>>>(gamma1, beta1);
    ew1_kernel<<<ewgrid, 256>>>(pY, x);
    // 11: conv3b -> Y; BN2; out = relu(bn + R)
    tconv_kernel<<<tgrid, NT, TCONV_SMEM>>>(pTh, pW32b, pn3b, 27, nullptr, nullptr, pY);
    bn_partial_kernel<<<64, 256>>>(pY);
    bn_finalize_kernel<<<1, 128>>>(gamma2, beta2);
    ew2_kernel<<<ewgrid, 256>>>(pY, out);
}